// round 13
// baseline (speedup 1.0000x reference)
#include <cuda_runtime.h>
#include <cuda_bf16.h>
#include <math.h>

#define BB 2
#define NN 2048
#define EE 64
#define HH 2
#define KK 2
#define FIN 18
#define MAXDEG_ADJ 64
#define MAXDEG_A2 512
#define MAXDEG_IN 64
#define FULLMASK 0xffffffffu

// ---------------- device scratch (static, no allocation) ----------------
__device__ float g_h[BB*NN*EE];
__device__ __align__(16) float g_zp[BB*NN*2*EE];   // fp32 z, packed [h0 e0..63 | h1 e0..63]
__device__ float g_ssrc[HH*BB*NN];
__device__ float g_sdst[HH*BB*NN];
__device__ float g_aggs[BB*NN*KK*EE];
__device__ unsigned short g_nbr_adj[BB*NN*MAXDEG_ADJ];
__device__ unsigned short g_nbr_a2[BB*NN*MAXDEG_A2];
__device__ unsigned short g_rin[BB*NN*MAXDEG_IN];
__device__ int g_deg_adj[BB*NN];
__device__ int g_deg_a2[BB*NN];
__device__ int g_rdeg[BB*NN];
// adjbit layout: word = (col>>7)*4 + (col&3), bit = (col>>2)&31
__device__ unsigned g_adjbit[BB*NN*(NN/32)];
__device__ float g_nw[BB*NN];
__device__ float g_dv[BB*NN];
__device__ float g_enw[BB*NN];
__device__ float g_Z[BB*NN];
__device__ float g_s10[BB*NN];
__device__ unsigned g_gmaxu[BB];

__device__ __forceinline__ float warpSum(float v){
    #pragma unroll
    for (int o=16;o;o>>=1) v += __shfl_xor_sync(FULLMASK, v, o);
    return v;
}
__device__ __forceinline__ float sigmoidf_(float x){ return 1.0f/(1.0f+__expf(-x)); }

// ---------------- encoder (+ prelude zeroing of counters/out) -------------
__global__ __launch_bounds__(256) void K_enc(const float* __restrict__ emb,
                                             const float* __restrict__ feat,
                                             const float* __restrict__ W0,
                                             const float* __restrict__ b0,
                                             const float* __restrict__ W1,
                                             const float* __restrict__ b1,
                                             float* __restrict__ out){
    int zidx = blockIdx.x*256 + threadIdx.x;
    if (zidx < BB*NN) g_rdeg[zidx] = 0;
    if (blockIdx.x == 0 && threadIdx.x < BB){ out[threadIdx.x] = 0.f; g_gmaxu[threadIdx.x] = 0u; }

    __shared__ float sW0[FIN*EE];
    __shared__ float sW1[EE*EE];
    __shared__ float sx[4][FIN];
    __shared__ float st[4][EE];
    int tid = threadIdx.x;
    for (int i = tid; i < FIN*EE; i += 256) sW0[i] = W0[i];
    for (int i = tid; i < EE*EE;  i += 256) sW1[i] = W1[i];
    int g = tid >> 6, e = tid & 63;
    int gn = blockIdx.x*4 + g;
    if (e < 16)       sx[g][e]   = emb[gn*16 + e];
    else if (e < 18)  sx[g][e]   = feat[gn*2 + (e-16)];
    __syncthreads();
    float acc = b0[e];
    #pragma unroll
    for (int d=0; d<FIN; d++) acc += sx[g][d]*sW0[d*EE+e];
    st[g][e] = tanhf(acc);
    __syncthreads();
    float acc2 = b1[e];
    #pragma unroll
    for (int d=0; d<EE; d++) acc2 += st[g][d]*sW1[d*EE+e];
    g_h[gn*EE+e] = tanhf(acc2);
}

// ---------------- CSR + bitset + reverse-CSR build (float4, MLP x4) -------
__global__ __launch_bounds__(256) void K_build(const float* __restrict__ neigh){
    int lane = threadIdx.x & 31;
    int row = blockIdx.x*8 + (threadIdx.x >> 5);
    int k  = row / (BB*NN);
    int bn = row % (BB*NN);
    int b_ = bn / NN, i_ = bn % NN;
    const float4* src4 = (const float4*)(neigh + (size_t)row * NN);
    unsigned short* dst = (k==0) ? (g_nbr_adj + (size_t)bn*MAXDEG_ADJ)
                                 : (g_nbr_a2  + (size_t)bn*MAXDEG_A2);
    int cap = (k==0) ? MAXDEG_ADJ : MAXDEG_A2;
    int deg = 0;
    unsigned below = (1u<<lane)-1u;
    #pragma unroll 2
    for (int c=0; c<NN/128; c++){
        float4 v = src4[c*32 + lane];
        bool p0 = v.x>0.0f, p1 = v.y>0.0f, p2 = v.z>0.0f, p3 = v.w>0.0f;
        unsigned ba0 = __ballot_sync(FULLMASK, p0);
        unsigned ba1 = __ballot_sync(FULLMASK, p1);
        unsigned ba2 = __ballot_sync(FULLMASK, p2);
        unsigned ba3 = __ballot_sync(FULLMASK, p3);
        if (k==0 && lane<4){
            unsigned sel = (lane==0)?ba0:(lane==1)?ba1:(lane==2)?ba2:ba3;
            g_adjbit[(size_t)bn*(NN/32) + c*4 + lane] = sel;
        }
        int base0 = deg;
        int base1 = base0 + __popc(ba0);
        int base2 = base1 + __popc(ba1);
        int base3 = base2 + __popc(ba2);
        int j0 = c*128 + lane*4;
        if (p0){ int p = base0 + __popc(ba0&below); if (p<cap) dst[p] = (unsigned short)j0;
                 if (k==0){ int rp = atomicAdd(&g_rdeg[b_*NN+j0],1); if (rp<MAXDEG_IN) g_rin[(size_t)(b_*NN+j0)*MAXDEG_IN+rp]=(unsigned short)i_; } }
        if (p1){ int p = base1 + __popc(ba1&below); if (p<cap) dst[p] = (unsigned short)(j0+1);
                 if (k==0){ int rp = atomicAdd(&g_rdeg[b_*NN+j0+1],1); if (rp<MAXDEG_IN) g_rin[(size_t)(b_*NN+j0+1)*MAXDEG_IN+rp]=(unsigned short)i_; } }
        if (p2){ int p = base2 + __popc(ba2&below); if (p<cap) dst[p] = (unsigned short)(j0+2);
                 if (k==0){ int rp = atomicAdd(&g_rdeg[b_*NN+j0+2],1); if (rp<MAXDEG_IN) g_rin[(size_t)(b_*NN+j0+2)*MAXDEG_IN+rp]=(unsigned short)i_; } }
        if (p3){ int p = base3 + __popc(ba3&below); if (p<cap) dst[p] = (unsigned short)(j0+3);
                 if (k==0){ int rp = atomicAdd(&g_rdeg[b_*NN+j0+3],1); if (rp<MAXDEG_IN) g_rin[(size_t)(b_*NN+j0+3)*MAXDEG_IN+rp]=(unsigned short)i_; } }
        deg = base3 + __popc(ba3);
    }
    if (lane==0){
        if (deg > cap) deg = cap;
        if (k==0) g_deg_adj[bn] = deg; else g_deg_a2[bn] = deg;
    }
}

// ---------------- z projection (fp32) + attention logits, 16 nodes/block --
__global__ __launch_bounds__(256) void K_z(const float* __restrict__ attn_W,
                                           const float* __restrict__ a_src,
                                           const float* __restrict__ a_dst){
    int h = blockIdx.y;
    __shared__ __align__(16) float sW[EE*EE];
    __shared__ __align__(16) float sh[16][68];
    int tid = threadIdx.x;
    const float* W = attn_W + h*EE*EE;
    for (int i=tid;i<EE*EE;i+=256) sW[i] = W[i];
    int gn0 = blockIdx.x*16;
    for (int i=tid;i<16*EE;i+=256) sh[i>>6][i&63] = g_h[(size_t)gn0*EE + i];
    __syncthreads();
    int eg = tid & 15;
    int ng = tid >> 4;       // one node per 16-lane group
    float4 acc = {0,0,0,0};
    const float4* sW4 = (const float4*)sW;
    #pragma unroll 4
    for (int d=0; d<EE; d++){
        float4 wv = sW4[d*16 + eg];
        float h0 = sh[ng][d];
        acc.x += h0*wv.x; acc.y += h0*wv.y; acc.z += h0*wv.z; acc.w += h0*wv.w;
    }
    *(float4*)(g_zp + ((size_t)(gn0+ng))*2*EE + h*EE + eg*4) = acc;
    const float4* as4 = (const float4*)(a_src + h*EE);
    const float4* ad4 = (const float4*)(a_dst + h*EE);
    float4 as = as4[eg], ad = ad4[eg];
    float p0 = acc.x*as.x + acc.y*as.y + acc.z*as.z + acc.w*as.w;
    float q0 = acc.x*ad.x + acc.y*ad.y + acc.z*ad.z + acc.w*ad.w;
    #pragma unroll
    for (int o=8;o;o>>=1){
        p0 += __shfl_down_sync(FULLMASK, p0, o, 16);
        q0 += __shfl_down_sync(FULLMASK, q0, o, 16);
    }
    if (eg == 0){
        g_ssrc[h*BB*NN + gn0 + ng] = p0;
        g_sdst[h*BB*NN + gn0 + ng] = q0;
    }
}

__device__ __forceinline__ void f32off_acc(const float* base, int off, int lane,
                                           float wt, float& a0, float& a1, float& a2, float& a3){
    float4 v = *((const float4*)(base + off) + lane);
    a0 += wt*v.x; a1 += wt*v.y; a2 += wt*v.z; a3 += wt*v.w;
}

// ---------------- a2 (k=1) aggregation: block per node --------------------
__global__ __launch_bounds__(256) void K_agg_a2(){
    int bn = blockIdx.x;
    int b  = bn >> 11;
    int tid = threadIdx.x, w = tid>>5, lane = tid&31;

    __shared__ float sacc[8][128];
    __shared__ float sw0s[8], sw1s[8];
    __shared__ int sj[8][32];          // pre-scaled float offsets (j*128)
    __shared__ float swt[8][2][32];

    int deg = g_deg_a2[bn];
    const unsigned short* list = g_nbr_a2 + (size_t)bn*MAXDEG_A2;
    const float* zb = g_zp + (size_t)b*NN*2*EE;

    float a0=0.f, a1=0.f, a2=0.f, a3=0.f;
    float s0=0.f, s1=0.f;
    if (deg == 0){
        for (int j = w*(NN/8); j < (w+1)*(NN/8); j++)
            f32off_acc(zb, j*128, lane, 1.0f, a0,a1,a2,a3);
        if (lane == 0){ s0 = (float)(NN/8); s1 = (float)(NN/8); }
    } else {
        float ssrc0 = g_ssrc[bn];
        float ssrc1 = g_ssrc[BB*NN + bn];
        const float* sd0 = g_sdst + b*NN;
        const float* sd1 = g_sdst + BB*NN + b*NN;
        const float* wrow = swt[w][lane>>4];
        for (int base = w*32; base < deg; base += 256){
            int cnt = deg - base; if (cnt > 32) cnt = 32;
            int jl = 0; float w0l = 0.f, w1l = 0.f;
            if (lane < cnt){
                jl = list[base + lane];
                w0l = __expf(tanhf(ssrc0 + sd0[jl]));
                w1l = __expf(tanhf(ssrc1 + sd1[jl]));
            }
            s0 += w0l; s1 += w1l;
            sj[w][lane] = jl*128;
            swt[w][0][lane] = w0l;
            swt[w][1][lane] = w1l;
            __syncwarp();
            if (cnt == 32){
                #pragma unroll 8
                for (int i=0;i<32;i++)
                    f32off_acc(zb, sj[w][i], lane, wrow[i], a0,a1,a2,a3);
            } else {
                for (int i=0;i<cnt;i++)
                    f32off_acc(zb, sj[w][i], lane, wrow[i], a0,a1,a2,a3);
            }
            __syncwarp();
        }
    }
    s0 = warpSum(s0); s1 = warpSum(s1);
    if (lane==0){ sw0s[w]=s0; sw1s[w]=s1; }
    sacc[w][lane*4+0]=a0; sacc[w][lane*4+1]=a1;
    sacc[w][lane*4+2]=a2; sacc[w][lane*4+3]=a3;
    __syncthreads();
    if (tid < EE){
        float r0=0.f, r1=0.f, S0=0.f, S1=0.f;
        #pragma unroll
        for (int ww=0; ww<8; ww++){
            r0 += sacc[ww][tid];
            r1 += sacc[ww][64+tid];
            S0 += sw0s[ww]; S1 += sw1s[ww];
        }
        float v = 0.5f*(r0/S0 + r1/S1);
        g_aggs[((size_t)bn*KK + 1)*EE + tid] = tanhf(v);
    }
}

// ---------------- adj (k=0) aggregation: warp per node --------------------
__global__ __launch_bounds__(256) void K_agg_adj(){
    int w = threadIdx.x>>5, lane = threadIdx.x&31;
    int bn = blockIdx.x*8 + w;
    int b = bn >> 11;
    __shared__ int sj[8][32];
    __shared__ float sw0_[8][32], sw1_[8][32];
    int deg = g_deg_adj[bn];
    const float* zb = g_zp + (size_t)b*NN*2*EE;
    float a0=0,a1=0,a2=0,a3=0, ws0=0, ws1=0;
    if (deg==0){
        for (int j=0;j<NN;j++) f32off_acc(zb, j*128, lane, 1.0f, a0,a1,a2,a3);
        ws0 = (float)NN; ws1 = (float)NN;
    } else {
        const unsigned short* list = g_nbr_adj + (size_t)bn*MAXDEG_ADJ;
        float ssrc0 = g_ssrc[bn], ssrc1 = g_ssrc[BB*NN+bn];
        const float* sd0 = g_sdst + b*NN;
        const float* sd1 = g_sdst + BB*NN + b*NN;
        const float* wrow = (lane<16) ? sw0_[w] : sw1_[w];
        for (int base=0; base<deg; base+=32){
            int cnt = deg - base; if (cnt>32) cnt=32;
            float w0 = 0.f, w1 = 0.f;
            if (lane < cnt){
                int j = list[base+lane];
                sj[w][lane] = j*128;
                w0 = __expf(tanhf(ssrc0 + sd0[j]));
                w1 = __expf(tanhf(ssrc1 + sd1[j]));
                sw0_[w][lane]=w0; sw1_[w][lane]=w1;
            }
            ws0 += w0; ws1 += w1;
            __syncwarp();
            #pragma unroll 8
            for (int i=0;i<cnt;i++)
                f32off_acc(zb, sj[w][i], lane, wrow[i], a0,a1,a2,a3);
            __syncwarp();
        }
        ws0 = warpSum(ws0); ws1 = warpSum(ws1);
    }
    float b0 = __shfl_down_sync(FULLMASK, a0, 16);
    float b1 = __shfl_down_sync(FULLMASK, a1, 16);
    float b2 = __shfl_down_sync(FULLMASK, a2, 16);
    float b3 = __shfl_down_sync(FULLMASK, a3, 16);
    if (lane < 16){
        float inv0 = 1.0f/ws0, inv1 = 1.0f/ws1;
        float4 o;
        o.x = tanhf(0.5f*(a0*inv0 + b0*inv1));
        o.y = tanhf(0.5f*(a1*inv0 + b1*inv1));
        o.z = tanhf(0.5f*(a2*inv0 + b2*inv1));
        o.w = tanhf(0.5f*(a3*inv0 + b3*inv1));
        *(float4*)(g_aggs + ((size_t)bn*KK+0)*EE + lane*4) = o;
    }
}

// ---------------- GRU as register-tiled GEMM (32 nodes/block) -------------
#define XS 132
#define ZS 68
__global__ __launch_bounds__(256) void K_gru(const float* __restrict__ nbr_q,
                                             const float* __restrict__ gru_W,
                                             const float* __restrict__ gru_U,
                                             const float* __restrict__ gru_b){
    extern __shared__ __align__(16) float dyn[];
    float* WA = dyn;                 // 128*128
    float* WB = dyn + 16384;         // 128*64
    float* X  = dyn + 24576;         // 32*XS
    float* SZ = X + 32*XS;           // 32*ZS (z gate)
    float* HO = SZ + 32*ZS;          // 32*ZS (h_old)
    int tid = threadIdx.x, w = tid>>5, lane = tid&31;

    for (int i=tid; i<128*128; i+=256){
        int d = i>>7, e = i&127;
        WA[i] = (d<64) ? gru_W[d*192+e] : gru_U[(d-64)*192+e];
    }
    for (int i=tid; i<128*64; i+=256){
        int d = i>>6, e = i&63;
        WB[i] = (d<64) ? gru_W[d*192+128+e] : gru_U[(d-64)*192+128+e];
    }

    int gn0 = blockIdx.x*32;
    for (int r=0; r<4; r++){
        int ln = w*4 + r;
        int gn = gn0 + ln;
        const float* ag = g_aggs + (size_t)gn*KK*EE;
        float a0_1 = ag[lane],     a0_2 = ag[32+lane];
        float a1_1 = ag[64+lane],  a1_2 = ag[96+lane];
        float q1 = nbr_q[lane], q2 = nbr_q[32+lane];
        float d0 = warpSum(a0_1*q1 + a0_2*q2);
        float d1 = warpSum(a1_1*q1 + a1_2*q2);
        float t0 = tanhf(d0), t1 = tanhf(d1);
        float mx = fmaxf(t0,t1);
        float ex0 = __expf(t0-mx), ex1 = __expf(t1-mx);
        float inv = 1.0f/(ex0+ex1);
        float c0 = ex0*inv, c1 = ex1*inv;
        float h1 = g_h[(size_t)gn*EE+lane], h2 = g_h[(size_t)gn*EE+32+lane];
        X[ln*XS+lane]      = c0*a0_1 + c1*a1_1;
        X[ln*XS+32+lane]   = c0*a0_2 + c1*a1_2;
        X[ln*XS+64+lane]   = h1;
        X[ln*XS+96+lane]   = h2;
        HO[ln*ZS+lane]     = h1;
        HO[ln*ZS+32+lane]  = h2;
    }
    __syncthreads();

    int ng = tid & 7;
    int eg = tid >> 3;

    float4 acA0={0,0,0,0}, acA1={0,0,0,0}, acA2={0,0,0,0}, acA3={0,0,0,0};
    {
        const float4* WA4 = (const float4*)WA;
        const float* x0p = X + ng*XS;
        const float* x1p = X + (ng+8)*XS;
        const float* x2p = X + (ng+16)*XS;
        const float* x3p = X + (ng+24)*XS;
        #pragma unroll 4
        for (int d=0; d<128; d++){
            float4 wv = WA4[d*32 + eg];
            float x0 = x0p[d], x1 = x1p[d], x2 = x2p[d], x3 = x3p[d];
            acA0.x += x0*wv.x; acA0.y += x0*wv.y; acA0.z += x0*wv.z; acA0.w += x0*wv.w;
            acA1.x += x1*wv.x; acA1.y += x1*wv.y; acA1.z += x1*wv.z; acA1.w += x1*wv.w;
            acA2.x += x2*wv.x; acA2.y += x2*wv.y; acA2.z += x2*wv.z; acA2.w += x2*wv.w;
            acA3.x += x3*wv.x; acA3.y += x3*wv.y; acA3.z += x3*wv.z; acA3.w += x3*wv.w;
        }
    }
    __syncthreads();
    {
        int e0 = eg*4;
        float b0v = gru_b[e0], b1v = gru_b[e0+1], b2v = gru_b[e0+2], b3v = gru_b[e0+3];
        float4 accs[4] = {acA0, acA1, acA2, acA3};
        #pragma unroll
        for (int k=0;k<4;k++){
            int n = ng + k*8;
            float v0 = sigmoidf_(accs[k].x + b0v);
            float v1 = sigmoidf_(accs[k].y + b1v);
            float v2 = sigmoidf_(accs[k].z + b2v);
            float v3 = sigmoidf_(accs[k].w + b3v);
            if (e0 < 64){
                SZ[n*ZS+e0]=v0; SZ[n*ZS+e0+1]=v1; SZ[n*ZS+e0+2]=v2; SZ[n*ZS+e0+3]=v3;
            } else {
                int c = e0;
                X[n*XS+c]   = v0 * X[n*XS+c];
                X[n*XS+c+1] = v1 * X[n*XS+c+1];
                X[n*XS+c+2] = v2 * X[n*XS+c+2];
                X[n*XS+c+3] = v3 * X[n*XS+c+3];
            }
        }
    }
    __syncthreads();

    float acB0x=0,acB0y=0, acB1x=0,acB1y=0, acB2x=0,acB2y=0, acB3x=0,acB3y=0;
    {
        const float2* WB2 = (const float2*)WB;
        const float* x0p = X + ng*XS;
        const float* x1p = X + (ng+8)*XS;
        const float* x2p = X + (ng+16)*XS;
        const float* x3p = X + (ng+24)*XS;
        #pragma unroll 4
        for (int d=0; d<128; d++){
            float2 wv = WB2[d*32 + eg];
            float x0 = x0p[d], x1 = x1p[d], x2 = x2p[d], x3 = x3p[d];
            acB0x += x0*wv.x; acB0y += x0*wv.y;
            acB1x += x1*wv.x; acB1y += x1*wv.y;
            acB2x += x2*wv.x; acB2y += x2*wv.y;
            acB3x += x3*wv.x; acB3y += x3*wv.y;
        }
    }
    {
        int e0 = eg*2;
        float bb0 = gru_b[128+e0], bb1 = gru_b[128+e0+1];
        float bx[4] = {acB0x, acB1x, acB2x, acB3x};
        float by[4] = {acB0y, acB1y, acB2y, acB3y};
        #pragma unroll
        for (int k=0;k<4;k++){
            int n = ng + k*8;
            int gn = gn0 + n;
            float ht0 = tanhf(bx[k] + bb0);
            float ht1 = tanhf(by[k] + bb1);
            float z0 = SZ[n*ZS+e0], z1 = SZ[n*ZS+e0+1];
            float h0 = HO[n*ZS+e0], h1 = HO[n*ZS+e0+1];
            g_h[(size_t)gn*EE+e0]   = (1.0f-z0)*h0 + z0*ht0;
            g_h[(size_t)gn*EE+e0+1] = (1.0f-z1)*h1 + z1*ht1;
        }
    }
}
#define GRU_SMEM ((16384 + 128*64 + 32*XS + 2*32*ZS)*4)

// ---------------- decoder + dual heads as tiled GEMM + gmax ---------------
__global__ __launch_bounds__(256) void K_dec_dual(const float* __restrict__ dW0, const float* __restrict__ db0,
                                                  const float* __restrict__ dW1, const float* __restrict__ db1,
                                                  const float* __restrict__ uW0, const float* __restrict__ ub0,
                                                  const float* __restrict__ uW1, const float* __restrict__ ub1){
    extern __shared__ __align__(16) float ddyn[];
    float* WC = ddyn;               // 64*128 (cols: 0..63 dec, 64..127 dual)
    float* X  = ddyn + 8192;        // 32*ZS
    float* T  = X + 32*ZS;          // 32*XS (tanh outputs, 128 per node)
    int tid = threadIdx.x, w = tid>>5, lane = tid&31;

    for (int i=tid; i<64*128; i+=256){
        int d = i>>7, e = i&127;
        WC[i] = (e<64) ? dW0[d*64+e] : uW0[d*64+(e-64)];
    }
    int gn0 = blockIdx.x*32;
    for (int i=tid; i<32*64; i+=256) X[(i>>6)*ZS + (i&63)] = g_h[(size_t)gn0*EE + i];
    __syncthreads();

    int ng = tid & 7;
    int eg = tid >> 3;
    float4 ac0={0,0,0,0}, ac1={0,0,0,0}, ac2={0,0,0,0}, ac3={0,0,0,0};
    {
        const float4* WC4 = (const float4*)WC;
        const float* x0p = X + ng*ZS;
        const float* x1p = X + (ng+8)*ZS;
        const float* x2p = X + (ng+16)*ZS;
        const float* x3p = X + (ng+24)*ZS;
        #pragma unroll 4
        for (int d=0; d<64; d++){
            float4 wv = WC4[d*32 + eg];
            float x0 = x0p[d], x1 = x1p[d], x2 = x2p[d], x3 = x3p[d];
            ac0.x += x0*wv.x; ac0.y += x0*wv.y; ac0.z += x0*wv.z; ac0.w += x0*wv.w;
            ac1.x += x1*wv.x; ac1.y += x1*wv.y; ac1.z += x1*wv.z; ac1.w += x1*wv.w;
            ac2.x += x2*wv.x; ac2.y += x2*wv.y; ac2.z += x2*wv.z; ac2.w += x2*wv.w;
            ac3.x += x3*wv.x; ac3.y += x3*wv.y; ac3.z += x3*wv.z; ac3.w += x3*wv.w;
        }
    }
    {
        int e0 = eg*4;
        float b0v = (e0<64) ? db0[e0]   : ub0[e0-64];
        float b1v = (e0<64) ? db0[e0+1] : ub0[e0-63];
        float b2v = (e0<64) ? db0[e0+2] : ub0[e0-62];
        float b3v = (e0<64) ? db0[e0+3] : ub0[e0-61];
        float4 accs[4] = {ac0, ac1, ac2, ac3};
        #pragma unroll
        for (int k=0;k<4;k++){
            int n = ng + k*8;
            T[n*XS+e0]   = tanhf(accs[k].x + b0v);
            T[n*XS+e0+1] = tanhf(accs[k].y + b1v);
            T[n*XS+e0+2] = tanhf(accs[k].z + b2v);
            T[n*XS+e0+3] = tanhf(accs[k].w + b3v);
        }
    }
    __syncthreads();
    // reduction: warp w handles nodes w*4 .. w*4+3
    float w1a = dW1[lane], w1b = dW1[lane+32];
    float v1a = uW1[lane], v1b = uW1[lane+32];
    for (int r=0; r<4; r++){
        int ln = w*4 + r;
        int gn = gn0 + ln;
        float p = warpSum(T[ln*XS+lane]*w1a + T[ln*XS+32+lane]*w1b);
        float q = warpSum(T[ln*XS+64+lane]*v1a + T[ln*XS+96+lane]*v1b);
        if (lane==0){
            float nwv = p + db1[0];
            g_nw[gn] = nwv;
            unsigned u = __float_as_uint(nwv);
            u = (u & 0x80000000u) ? ~u : (u | 0x80000000u);
            atomicMax(&g_gmaxu[gn>>11], u);
            g_dv[gn] = q + ub1[0];
        }
    }
}
#define DD_SMEM ((8192 + 32*ZS + 32*XS)*4)

// ---------------- softmax denominators + exp(nw) ----------------
__global__ __launch_bounds__(256) void K_prop(){
    int w = threadIdx.x>>5, lane = threadIdx.x&31;
    int gn = blockIdx.x*8 + w;
    int b = gn >> 11;
    unsigned u = g_gmaxu[b];
    float gm = __uint_as_float((u & 0x80000000u) ? (u ^ 0x80000000u) : ~u);
    int deg = g_deg_adj[gn];
    const unsigned short* list = g_nbr_adj + (size_t)gn*MAXDEG_ADJ;
    float s = 0.f;
    for (int t=lane; t<deg; t+=32) s += __expf(g_nw[b*NN + list[t]] - gm);
    s = warpSum(s);
    if (lane==0){
        g_Z[gn] = (deg>0) ? s : 1.0f;
        g_enw[gn] = __expf(g_nw[gn] - gm);
    }
}

// ---------------- fused 10-iteration MCF, reverse-CSR gather --------------
__global__ __launch_bounds__(1024) void K_flow(const float* __restrict__ demands){
    int b = blockIdx.x;
    __shared__ float us[NN];
    int n1 = threadIdx.x, n2 = threadIdx.x + 1024;
    int gn1 = b*NN+n1, gn2 = b*NN+n2;
    float invZ1 = 1.0f/g_Z[gn1], invZ2 = 1.0f/g_Z[gn2];
    float d1 = demands[gn1], d2 = demands[gn2];
    float e1 = g_enw[gn1],  e2 = g_enw[gn2];
    int rd1 = min(g_rdeg[gn1], MAXDEG_IN);
    int rd2 = min(g_rdeg[gn2], MAXDEG_IN);
    const unsigned short* l1 = g_rin + (size_t)gn1*MAXDEG_IN;
    const unsigned short* l2 = g_rin + (size_t)gn2*MAXDEG_IN;
    float s1 = 0.f, s2 = 0.f;
    for (int it=0; it<10; it++){
        us[n1] = s1*invZ1; us[n2] = s2*invZ2;
        __syncthreads();
        float a1 = 0.f, a2 = 0.f;
        for (int t=0; t<rd1; t++) a1 += us[l1[t]];
        for (int t=0; t<rd2; t++) a2 += us[l2[t]];
        s1 = fmaxf(fmaf(e1, a1, -d1), 0.f);
        s2 = fmaxf(fmaf(e2, a2, -d2), 0.f);
        __syncthreads();
    }
    g_s10[gn1] = s1;
    g_s10[gn2] = s2;
}

// ---------------- flow cost + dual iterations + final reduction ----------
__global__ __launch_bounds__(256) void K_final(const float* __restrict__ demands,
                                               float* __restrict__ out){
    int b = blockIdx.y;
    int tid = threadIdx.x, w = tid>>5, lane = tid&31;
    float acc = 0.f;
    for (int idx = w; idx < 64; idx += 8){
        int n = blockIdx.x*64 + idx;
        int gn = b*NN+n;
        int deg = g_deg_adj[gn];
        const unsigned short* list = g_nbr_adj + (size_t)gn*MAXDEG_ADJ;
        float si = g_s10[gn];
        float invZi = 1.0f/g_Z[gn];
        float dvi = g_dv[gn];
        float enwi = g_enw[gn];
        if (lane==0) acc += dvi * demands[gn];
        int word_idx = (n>>7)*4 + (n&3);
        int bit_idx  = (n>>2)&31;
        for (int t=lane; t<deg; t+=32){
            int j = list[t];
            int gj = b*NN+j;
            float f = g_enw[gj]*invZi*si;
            unsigned word = g_adjbit[(size_t)gj*(NN/32) + word_idx];
            float ft = 0.f;
            if ((word >> bit_idx) & 1u) ft = enwi * (g_s10[gj]/g_Z[gj]);
            float fp = f - fminf(f, ft);
            acc += fp*fp;
            float dd = dvi - g_dv[gj];
            float y = 0.f, m = 0.f;
            #pragma unroll
            for (int q=0; q<10; q++){
                float gg = 2.0f*y - dd;
                m = 0.9f*m + gg;
                y = fmaxf(y - 0.1f*m, 0.f);
            }
            acc -= (y*y - dd*y);
        }
    }
    acc = warpSum(acc);
    __shared__ float sr[8];
    if (lane==0) sr[w] = acc;
    __syncthreads();
    if (tid==0){
        float t = 0.f; for (int i=0;i<8;i++) t += sr[i];
        atomicAdd(&out[b], t);
    }
}

// ---------------- launch ----------------
extern "C" void kernel_launch(void* const* d_in, const int* in_sizes, int n_in,
                              void* d_out, int out_size){
    const float* feat    = (const float*)d_in[0];
    const float* emb     = (const float*)d_in[1];
    const float* demands = (const float*)d_in[2];
    const float* neigh   = (const float*)d_in[4];
    const float* enc_W0  = (const float*)d_in[5];
    const float* enc_b0  = (const float*)d_in[6];
    const float* enc_W1  = (const float*)d_in[7];
    const float* enc_b1  = (const float*)d_in[8];
    const float* attn_W  = (const float*)d_in[9];
    const float* a_src   = (const float*)d_in[10];
    const float* a_dst   = (const float*)d_in[11];
    const float* nbr_q   = (const float*)d_in[12];
    const float* gru_W   = (const float*)d_in[13];
    const float* gru_U   = (const float*)d_in[14];
    const float* gru_b   = (const float*)d_in[15];
    const float* dec_W0  = (const float*)d_in[16];
    const float* dec_b0  = (const float*)d_in[17];
    const float* dec_W1  = (const float*)d_in[18];
    const float* dec_b1  = (const float*)d_in[19];
    const float* dual_W0 = (const float*)d_in[20];
    const float* dual_b0 = (const float*)d_in[21];
    const float* dual_W1 = (const float*)d_in[22];
    const float* dual_b1 = (const float*)d_in[23];
    float* out = (float*)d_out;

    static int configured = 0;
    if (!configured){
        cudaFuncSetAttribute(K_gru, cudaFuncAttributeMaxDynamicSharedMemorySize, GRU_SMEM);
        cudaFuncSetAttribute(K_dec_dual, cudaFuncAttributeMaxDynamicSharedMemorySize, DD_SMEM);
        configured = 1;
    }

    // NOTE: ncu window captures the 4th launch -> K_agg_a2 (layer 0)
    K_enc<<<BB*NN/4,256>>>(emb, feat, enc_W0, enc_b0, enc_W1, enc_b1, out);
    K_build<<<KK*BB*NN/8,256>>>(neigh);
    for (int l=0;l<2;l++){
        K_z<<<dim3(BB*NN/16,HH),256>>>(attn_W, a_src, a_dst);
        K_agg_a2<<<BB*NN,256>>>();
        K_agg_adj<<<BB*NN/8,256>>>();
        K_gru<<<BB*NN/32,256, GRU_SMEM>>>(nbr_q, gru_W, gru_U, gru_b);
    }
    K_dec_dual<<<BB*NN/32,256, DD_SMEM>>>(dec_W0,dec_b0,dec_W1,dec_b1,dual_W0,dual_b0,dual_W1,dual_b1);
    K_prop<<<BB*NN/8,256>>>();
    K_flow<<<BB,1024>>>(demands);
    K_final<<<dim3(NN/64,BB),256>>>(demands, out);
}

// round 14
// speedup vs baseline: 1.0909x; 1.0909x over previous
#include <cuda_runtime.h>
#include <cuda_bf16.h>
#include <math.h>

#define BB 2
#define NN 2048
#define EE 64
#define HH 2
#define KK 2
#define FIN 18
#define MAXDEG_ADJ 64
#define MAXDEG_A2 512
#define MAXDEG_IN 64
#define FULLMASK 0xffffffffu

// ---------------- device scratch (static, no allocation) ----------------
__device__ float g_h[BB*NN*EE];
__device__ __align__(256) __nv_bfloat16 g_zb[BB*NN*2*EE];  // bf16 z, packed [h0 e0..63 | h1 e0..63]
__device__ float g_ssrc[HH*BB*NN];
__device__ float g_sdst[HH*BB*NN];
__device__ float g_aggs[BB*NN*KK*EE];
__device__ unsigned short g_nbr_adj[BB*NN*MAXDEG_ADJ];
__device__ unsigned short g_nbr_a2[BB*NN*MAXDEG_A2];
__device__ unsigned short g_rin[BB*NN*MAXDEG_IN];
__device__ int g_deg_adj[BB*NN];
__device__ int g_deg_a2[BB*NN];
__device__ int g_rdeg[BB*NN];
// adjbit layout: word = (col>>7)*4 + (col&3), bit = (col>>2)&31
__device__ unsigned g_adjbit[BB*NN*(NN/32)];
__device__ float g_nw[BB*NN];
__device__ float g_dv[BB*NN];
__device__ float g_enw[BB*NN];
__device__ float g_Z[BB*NN];
__device__ float g_s10[BB*NN];
__device__ unsigned g_gmaxu[BB];

__device__ __forceinline__ float warpSum(float v){
    #pragma unroll
    for (int o=16;o;o>>=1) v += __shfl_xor_sync(FULLMASK, v, o);
    return v;
}
__device__ __forceinline__ float sigmoidf_(float x){ return 1.0f/(1.0f+__expf(-x)); }

// ---------------- encoder (+ prelude zeroing of counters/out) -------------
__global__ __launch_bounds__(256) void K_enc(const float* __restrict__ emb,
                                             const float* __restrict__ feat,
                                             const float* __restrict__ W0,
                                             const float* __restrict__ b0,
                                             const float* __restrict__ W1,
                                             const float* __restrict__ b1,
                                             float* __restrict__ out){
    int zidx = blockIdx.x*256 + threadIdx.x;
    if (zidx < BB*NN) g_rdeg[zidx] = 0;
    if (blockIdx.x == 0 && threadIdx.x < BB){ out[threadIdx.x] = 0.f; g_gmaxu[threadIdx.x] = 0u; }

    __shared__ float sW0[FIN*EE];
    __shared__ float sW1[EE*EE];
    __shared__ float sx[4][FIN];
    __shared__ float st[4][EE];
    int tid = threadIdx.x;
    for (int i = tid; i < FIN*EE; i += 256) sW0[i] = W0[i];
    for (int i = tid; i < EE*EE;  i += 256) sW1[i] = W1[i];
    int g = tid >> 6, e = tid & 63;
    int gn = blockIdx.x*4 + g;
    if (e < 16)       sx[g][e]   = emb[gn*16 + e];
    else if (e < 18)  sx[g][e]   = feat[gn*2 + (e-16)];
    __syncthreads();
    float acc = b0[e];
    #pragma unroll
    for (int d=0; d<FIN; d++) acc += sx[g][d]*sW0[d*EE+e];
    st[g][e] = tanhf(acc);
    __syncthreads();
    float acc2 = b1[e];
    #pragma unroll
    for (int d=0; d<EE; d++) acc2 += st[g][d]*sW1[d*EE+e];
    g_h[gn*EE+e] = tanhf(acc2);
}

// ---------------- CSR + bitset + reverse-CSR build (float4, MLP x4) -------
__global__ __launch_bounds__(256) void K_build(const float* __restrict__ neigh){
    int lane = threadIdx.x & 31;
    int row = blockIdx.x*8 + (threadIdx.x >> 5);
    int k  = row / (BB*NN);
    int bn = row % (BB*NN);
    int b_ = bn / NN, i_ = bn % NN;
    const float4* src4 = (const float4*)(neigh + (size_t)row * NN);
    unsigned short* dst = (k==0) ? (g_nbr_adj + (size_t)bn*MAXDEG_ADJ)
                                 : (g_nbr_a2  + (size_t)bn*MAXDEG_A2);
    int cap = (k==0) ? MAXDEG_ADJ : MAXDEG_A2;
    int deg = 0;
    unsigned below = (1u<<lane)-1u;
    #pragma unroll 2
    for (int c=0; c<NN/128; c++){
        float4 v = src4[c*32 + lane];
        bool p0 = v.x>0.0f, p1 = v.y>0.0f, p2 = v.z>0.0f, p3 = v.w>0.0f;
        unsigned ba0 = __ballot_sync(FULLMASK, p0);
        unsigned ba1 = __ballot_sync(FULLMASK, p1);
        unsigned ba2 = __ballot_sync(FULLMASK, p2);
        unsigned ba3 = __ballot_sync(FULLMASK, p3);
        if (k==0 && lane<4){
            unsigned sel = (lane==0)?ba0:(lane==1)?ba1:(lane==2)?ba2:ba3;
            g_adjbit[(size_t)bn*(NN/32) + c*4 + lane] = sel;
        }
        int base0 = deg;
        int base1 = base0 + __popc(ba0);
        int base2 = base1 + __popc(ba1);
        int base3 = base2 + __popc(ba2);
        int j0 = c*128 + lane*4;
        if (p0){ int p = base0 + __popc(ba0&below); if (p<cap) dst[p] = (unsigned short)j0;
                 if (k==0){ int rp = atomicAdd(&g_rdeg[b_*NN+j0],1); if (rp<MAXDEG_IN) g_rin[(size_t)(b_*NN+j0)*MAXDEG_IN+rp]=(unsigned short)i_; } }
        if (p1){ int p = base1 + __popc(ba1&below); if (p<cap) dst[p] = (unsigned short)(j0+1);
                 if (k==0){ int rp = atomicAdd(&g_rdeg[b_*NN+j0+1],1); if (rp<MAXDEG_IN) g_rin[(size_t)(b_*NN+j0+1)*MAXDEG_IN+rp]=(unsigned short)i_; } }
        if (p2){ int p = base2 + __popc(ba2&below); if (p<cap) dst[p] = (unsigned short)(j0+2);
                 if (k==0){ int rp = atomicAdd(&g_rdeg[b_*NN+j0+2],1); if (rp<MAXDEG_IN) g_rin[(size_t)(b_*NN+j0+2)*MAXDEG_IN+rp]=(unsigned short)i_; } }
        if (p3){ int p = base3 + __popc(ba3&below); if (p<cap) dst[p] = (unsigned short)(j0+3);
                 if (k==0){ int rp = atomicAdd(&g_rdeg[b_*NN+j0+3],1); if (rp<MAXDEG_IN) g_rin[(size_t)(b_*NN+j0+3)*MAXDEG_IN+rp]=(unsigned short)i_; } }
        deg = base3 + __popc(ba3);
    }
    if (lane==0){
        if (deg > cap) deg = cap;
        if (k==0) g_deg_adj[bn] = deg; else g_deg_a2[bn] = deg;
    }
}

// ---------------- z projection (bf16 out) + attention logits --------------
__global__ __launch_bounds__(256) void K_z(const float* __restrict__ attn_W,
                                           const float* __restrict__ a_src,
                                           const float* __restrict__ a_dst){
    int h = blockIdx.y;
    __shared__ __align__(16) float sW[EE*EE];
    __shared__ __align__(16) float sh[32][68];
    int tid = threadIdx.x;
    const float* W = attn_W + h*EE*EE;
    for (int i=tid;i<EE*EE;i+=256) sW[i] = W[i];
    int gn0 = blockIdx.x*32;
    for (int i=tid;i<32*EE;i+=256) sh[i>>6][i&63] = g_h[(size_t)gn0*EE + i];
    __syncthreads();
    int eg = tid & 15;
    int ng = tid >> 4;
    int n0 = ng*2, n1 = ng*2+1;
    float4 acc0 = {0,0,0,0}, acc1 = {0,0,0,0};
    const float4* sW4 = (const float4*)sW;
    #pragma unroll 4
    for (int d=0; d<EE; d++){
        float4 wv = sW4[d*16 + eg];
        float h0 = sh[n0][d];
        float h1 = sh[n1][d];
        acc0.x += h0*wv.x; acc0.y += h0*wv.y; acc0.z += h0*wv.z; acc0.w += h0*wv.w;
        acc1.x += h1*wv.x; acc1.y += h1*wv.y; acc1.z += h1*wv.z; acc1.w += h1*wv.w;
    }
    {
        __nv_bfloat162 b01 = __floats2bfloat162_rn(acc0.x, acc0.y);
        __nv_bfloat162 b23 = __floats2bfloat162_rn(acc0.z, acc0.w);
        uint2 u; u.x = *(unsigned*)&b01; u.y = *(unsigned*)&b23;
        *(uint2*)(g_zb + ((size_t)(gn0+n0))*2*EE + h*EE + eg*4) = u;
        b01 = __floats2bfloat162_rn(acc1.x, acc1.y);
        b23 = __floats2bfloat162_rn(acc1.z, acc1.w);
        u.x = *(unsigned*)&b01; u.y = *(unsigned*)&b23;
        *(uint2*)(g_zb + ((size_t)(gn0+n1))*2*EE + h*EE + eg*4) = u;
    }
    const float4* as4 = (const float4*)(a_src + h*EE);
    const float4* ad4 = (const float4*)(a_dst + h*EE);
    float4 as = as4[eg], ad = ad4[eg];
    float p0 = acc0.x*as.x + acc0.y*as.y + acc0.z*as.z + acc0.w*as.w;
    float q0 = acc0.x*ad.x + acc0.y*ad.y + acc0.z*ad.z + acc0.w*ad.w;
    float p1 = acc1.x*as.x + acc1.y*as.y + acc1.z*as.z + acc1.w*as.w;
    float q1 = acc1.x*ad.x + acc1.y*ad.y + acc1.z*ad.z + acc1.w*ad.w;
    #pragma unroll
    for (int o=8;o;o>>=1){
        p0 += __shfl_down_sync(FULLMASK, p0, o, 16);
        q0 += __shfl_down_sync(FULLMASK, q0, o, 16);
        p1 += __shfl_down_sync(FULLMASK, p1, o, 16);
        q1 += __shfl_down_sync(FULLMASK, q1, o, 16);
    }
    if (eg == 0){
        g_ssrc[h*BB*NN + gn0 + n0] = p0;
        g_sdst[h*BB*NN + gn0 + n0] = q0;
        g_ssrc[h*BB*NN + gn0 + n1] = p1;
        g_sdst[h*BB*NN + gn0 + n1] = q1;
    }
}

__device__ __forceinline__ void bf16off_acc(const __nv_bfloat16* base, int off, int lane4,
                                            float wt, float& a0, float& a1, float& a2, float& a3){
    uint2 u = *(const uint2*)(base + off + lane4);
    __nv_bfloat162 lo = *reinterpret_cast<__nv_bfloat162*>(&u.x);
    __nv_bfloat162 hi = *reinterpret_cast<__nv_bfloat162*>(&u.y);
    float2 f01 = __bfloat1622float2(lo);
    float2 f23 = __bfloat1622float2(hi);
    a0 += wt*f01.x; a1 += wt*f01.y; a2 += wt*f23.x; a3 += wt*f23.y;
}

// ---------------- a2 (k=1) aggregation: block per node --------------------
__global__ __launch_bounds__(256) void K_agg_a2(){
    int bn = blockIdx.x;
    int b  = bn >> 11;
    int tid = threadIdx.x, w = tid>>5, lane = tid&31;

    __shared__ float sacc[8][128];
    __shared__ float sw0s[8], sw1s[8];
    __shared__ int sj[8][32];          // pre-scaled element offsets (j*128)
    __shared__ float swt[8][2][32];

    int deg = g_deg_a2[bn];
    const unsigned short* list = g_nbr_a2 + (size_t)bn*MAXDEG_A2;
    const __nv_bfloat16* zb = g_zb + (size_t)b*NN*2*EE;

    float a0=0.f, a1=0.f, a2=0.f, a3=0.f;
    float s0=0.f, s1=0.f;
    int lane4 = lane*4;
    if (deg == 0){
        for (int j = w*(NN/8); j < (w+1)*(NN/8); j++)
            bf16off_acc(zb, j*128, lane4, 1.0f, a0,a1,a2,a3);
        if (lane == 0){ s0 = (float)(NN/8); s1 = (float)(NN/8); }
    } else {
        float ssrc0 = g_ssrc[bn];
        float ssrc1 = g_ssrc[BB*NN + bn];
        const float* sd0 = g_sdst + b*NN;
        const float* sd1 = g_sdst + BB*NN + b*NN;
        const float* wrow = swt[w][lane>>4];
        for (int base = w*32; base < deg; base += 256){
            int cnt = deg - base; if (cnt > 32) cnt = 32;
            int jl = 0; float w0l = 0.f, w1l = 0.f;
            if (lane < cnt){
                jl = list[base + lane];
                w0l = __expf(tanhf(ssrc0 + sd0[jl]));
                w1l = __expf(tanhf(ssrc1 + sd1[jl]));
            }
            s0 += w0l; s1 += w1l;
            sj[w][lane] = jl*128;
            swt[w][0][lane] = w0l;
            swt[w][1][lane] = w1l;
            __syncwarp();
            if (cnt == 32){
                #pragma unroll 8
                for (int i=0;i<32;i++)
                    bf16off_acc(zb, sj[w][i], lane4, wrow[i], a0,a1,a2,a3);
            } else {
                for (int i=0;i<cnt;i++)
                    bf16off_acc(zb, sj[w][i], lane4, wrow[i], a0,a1,a2,a3);
            }
            __syncwarp();
        }
    }
    s0 = warpSum(s0); s1 = warpSum(s1);
    if (lane==0){ sw0s[w]=s0; sw1s[w]=s1; }
    sacc[w][lane4+0]=a0; sacc[w][lane4+1]=a1;
    sacc[w][lane4+2]=a2; sacc[w][lane4+3]=a3;
    __syncthreads();
    if (tid < EE){
        float r0=0.f, r1=0.f, S0=0.f, S1=0.f;
        #pragma unroll
        for (int ww=0; ww<8; ww++){
            r0 += sacc[ww][tid];
            r1 += sacc[ww][64+tid];
            S0 += sw0s[ww]; S1 += sw1s[ww];
        }
        float v = 0.5f*(r0/S0 + r1/S1);
        g_aggs[((size_t)bn*KK + 1)*EE + tid] = tanhf(v);
    }
}

// ---------------- adj (k=0) aggregation: warp per node --------------------
__global__ __launch_bounds__(256) void K_agg_adj(){
    int w = threadIdx.x>>5, lane = threadIdx.x&31;
    int bn = blockIdx.x*8 + w;
    int b = bn >> 11;
    __shared__ int sj[8][32];
    __shared__ float sw0_[8][32], sw1_[8][32];
    int deg = g_deg_adj[bn];
    const __nv_bfloat16* zb = g_zb + (size_t)b*NN*2*EE;
    float a0=0,a1=0,a2=0,a3=0, ws0=0, ws1=0;
    int lane4 = lane*4;
    if (deg==0){
        for (int j=0;j<NN;j++) bf16off_acc(zb, j*128, lane4, 1.0f, a0,a1,a2,a3);
        ws0 = (float)NN; ws1 = (float)NN;
    } else {
        const unsigned short* list = g_nbr_adj + (size_t)bn*MAXDEG_ADJ;
        float ssrc0 = g_ssrc[bn], ssrc1 = g_ssrc[BB*NN+bn];
        const float* sd0 = g_sdst + b*NN;
        const float* sd1 = g_sdst + BB*NN + b*NN;
        const float* wrow = (lane<16) ? sw0_[w] : sw1_[w];
        for (int base=0; base<deg; base+=32){
            int cnt = deg - base; if (cnt>32) cnt=32;
            float w0 = 0.f, w1 = 0.f;
            if (lane < cnt){
                int j = list[base+lane];
                sj[w][lane] = j*128;
                w0 = __expf(tanhf(ssrc0 + sd0[j]));
                w1 = __expf(tanhf(ssrc1 + sd1[j]));
                sw0_[w][lane]=w0; sw1_[w][lane]=w1;
            }
            ws0 += w0; ws1 += w1;
            __syncwarp();
            #pragma unroll 8
            for (int i=0;i<cnt;i++)
                bf16off_acc(zb, sj[w][i], lane4, wrow[i], a0,a1,a2,a3);
            __syncwarp();
        }
        ws0 = warpSum(ws0); ws1 = warpSum(ws1);
    }
    float b0 = __shfl_down_sync(FULLMASK, a0, 16);
    float b1 = __shfl_down_sync(FULLMASK, a1, 16);
    float b2 = __shfl_down_sync(FULLMASK, a2, 16);
    float b3 = __shfl_down_sync(FULLMASK, a3, 16);
    if (lane < 16){
        float inv0 = 1.0f/ws0, inv1 = 1.0f/ws1;
        float4 o;
        o.x = tanhf(0.5f*(a0*inv0 + b0*inv1));
        o.y = tanhf(0.5f*(a1*inv0 + b1*inv1));
        o.z = tanhf(0.5f*(a2*inv0 + b2*inv1));
        o.w = tanhf(0.5f*(a3*inv0 + b3*inv1));
        *(float4*)(g_aggs + ((size_t)bn*KK+0)*EE + lane*4) = o;
    }
}

// ---------------- GRU as register-tiled GEMM (32 nodes/block) -------------
#define XS 132
#define ZS 68
__global__ __launch_bounds__(256) void K_gru(const float* __restrict__ nbr_q,
                                             const float* __restrict__ gru_W,
                                             const float* __restrict__ gru_U,
                                             const float* __restrict__ gru_b){
    extern __shared__ __align__(16) float dyn[];
    float* WA = dyn;                 // 128*128
    float* WB = dyn + 16384;         // 128*64
    float* X  = dyn + 24576;         // 32*XS
    float* SZ = X + 32*XS;           // 32*ZS (z gate)
    float* HO = SZ + 32*ZS;          // 32*ZS (h_old)
    int tid = threadIdx.x, w = tid>>5, lane = tid&31;

    for (int i=tid; i<128*128; i+=256){
        int d = i>>7, e = i&127;
        WA[i] = (d<64) ? gru_W[d*192+e] : gru_U[(d-64)*192+e];
    }
    for (int i=tid; i<128*64; i+=256){
        int d = i>>6, e = i&63;
        WB[i] = (d<64) ? gru_W[d*192+128+e] : gru_U[(d-64)*192+128+e];
    }

    int gn0 = blockIdx.x*32;
    for (int r=0; r<4; r++){
        int ln = w*4 + r;
        int gn = gn0 + ln;
        const float* ag = g_aggs + (size_t)gn*KK*EE;
        float a0_1 = ag[lane],     a0_2 = ag[32+lane];
        float a1_1 = ag[64+lane],  a1_2 = ag[96+lane];
        float q1 = nbr_q[lane], q2 = nbr_q[32+lane];
        float d0 = warpSum(a0_1*q1 + a0_2*q2);
        float d1 = warpSum(a1_1*q1 + a1_2*q2);
        float t0 = tanhf(d0), t1 = tanhf(d1);
        float mx = fmaxf(t0,t1);
        float ex0 = __expf(t0-mx), ex1 = __expf(t1-mx);
        float inv = 1.0f/(ex0+ex1);
        float c0 = ex0*inv, c1 = ex1*inv;
        float h1 = g_h[(size_t)gn*EE+lane], h2 = g_h[(size_t)gn*EE+32+lane];
        X[ln*XS+lane]      = c0*a0_1 + c1*a1_1;
        X[ln*XS+32+lane]   = c0*a0_2 + c1*a1_2;
        X[ln*XS+64+lane]   = h1;
        X[ln*XS+96+lane]   = h2;
        HO[ln*ZS+lane]     = h1;
        HO[ln*ZS+32+lane]  = h2;
    }
    __syncthreads();

    int ng = tid & 7;
    int eg = tid >> 3;

    float4 acA0={0,0,0,0}, acA1={0,0,0,0}, acA2={0,0,0,0}, acA3={0,0,0,0};
    {
        const float4* WA4 = (const float4*)WA;
        const float* x0p = X + ng*XS;
        const float* x1p = X + (ng+8)*XS;
        const float* x2p = X + (ng+16)*XS;
        const float* x3p = X + (ng+24)*XS;
        #pragma unroll 4
        for (int d=0; d<128; d++){
            float4 wv = WA4[d*32 + eg];
            float x0 = x0p[d], x1 = x1p[d], x2 = x2p[d], x3 = x3p[d];
            acA0.x += x0*wv.x; acA0.y += x0*wv.y; acA0.z += x0*wv.z; acA0.w += x0*wv.w;
            acA1.x += x1*wv.x; acA1.y += x1*wv.y; acA1.z += x1*wv.z; acA1.w += x1*wv.w;
            acA2.x += x2*wv.x; acA2.y += x2*wv.y; acA2.z += x2*wv.z; acA2.w += x2*wv.w;
            acA3.x += x3*wv.x; acA3.y += x3*wv.y; acA3.z += x3*wv.z; acA3.w += x3*wv.w;
        }
    }
    __syncthreads();
    {
        int e0 = eg*4;
        float b0v = gru_b[e0], b1v = gru_b[e0+1], b2v = gru_b[e0+2], b3v = gru_b[e0+3];
        float4 accs[4] = {acA0, acA1, acA2, acA3};
        #pragma unroll
        for (int k=0;k<4;k++){
            int n = ng + k*8;
            float v0 = sigmoidf_(accs[k].x + b0v);
            float v1 = sigmoidf_(accs[k].y + b1v);
            float v2 = sigmoidf_(accs[k].z + b2v);
            float v3 = sigmoidf_(accs[k].w + b3v);
            if (e0 < 64){
                SZ[n*ZS+e0]=v0; SZ[n*ZS+e0+1]=v1; SZ[n*ZS+e0+2]=v2; SZ[n*ZS+e0+3]=v3;
            } else {
                int c = e0;
                X[n*XS+c]   = v0 * X[n*XS+c];
                X[n*XS+c+1] = v1 * X[n*XS+c+1];
                X[n*XS+c+2] = v2 * X[n*XS+c+2];
                X[n*XS+c+3] = v3 * X[n*XS+c+3];
            }
        }
    }
    __syncthreads();

    float acB0x=0,acB0y=0, acB1x=0,acB1y=0, acB2x=0,acB2y=0, acB3x=0,acB3y=0;
    {
        const float2* WB2 = (const float2*)WB;
        const float* x0p = X + ng*XS;
        const float* x1p = X + (ng+8)*XS;
        const float* x2p = X + (ng+16)*XS;
        const float* x3p = X + (ng+24)*XS;
        #pragma unroll 4
        for (int d=0; d<128; d++){
            float2 wv = WB2[d*32 + eg];
            float x0 = x0p[d], x1 = x1p[d], x2 = x2p[d], x3 = x3p[d];
            acB0x += x0*wv.x; acB0y += x0*wv.y;
            acB1x += x1*wv.x; acB1y += x1*wv.y;
            acB2x += x2*wv.x; acB2y += x2*wv.y;
            acB3x += x3*wv.x; acB3y += x3*wv.y;
        }
    }
    {
        int e0 = eg*2;
        float bb0 = gru_b[128+e0], bb1 = gru_b[128+e0+1];
        float bx[4] = {acB0x, acB1x, acB2x, acB3x};
        float by[4] = {acB0y, acB1y, acB2y, acB3y};
        #pragma unroll
        for (int k=0;k<4;k++){
            int n = ng + k*8;
            int gn = gn0 + n;
            float ht0 = tanhf(bx[k] + bb0);
            float ht1 = tanhf(by[k] + bb1);
            float z0 = SZ[n*ZS+e0], z1 = SZ[n*ZS+e0+1];
            float h0 = HO[n*ZS+e0], h1 = HO[n*ZS+e0+1];
            g_h[(size_t)gn*EE+e0]   = (1.0f-z0)*h0 + z0*ht0;
            g_h[(size_t)gn*EE+e0+1] = (1.0f-z1)*h1 + z1*ht1;
        }
    }
}
#define GRU_SMEM ((16384 + 128*64 + 32*XS + 2*32*ZS)*4)

// ---------------- decoder + dual heads + gmax ----------------
__global__ __launch_bounds__(256) void K_dec_dual(const float* __restrict__ dW0, const float* __restrict__ db0,
                                                  const float* __restrict__ dW1, const float* __restrict__ db1,
                                                  const float* __restrict__ uW0, const float* __restrict__ ub0,
                                                  const float* __restrict__ uW1, const float* __restrict__ ub1){
    __shared__ float sWd[EE*EE];
    __shared__ float sWu[EE*EE];
    __shared__ float shh[8][EE];
    int tid = threadIdx.x;
    for (int i=tid;i<EE*EE;i+=256){ sWd[i]=dW0[i]; sWu[i]=uW0[i]; }
    __syncthreads();
    int w = tid>>5, lane = tid&31;
    int e1 = lane, e2 = lane+32;
    #pragma unroll
    for (int rep=0; rep<2; rep++){
        int gn = blockIdx.x*16 + w + rep*8;
        float h1 = g_h[(size_t)gn*EE+e1], h2 = g_h[(size_t)gn*EE+e2];
        shh[w][e1]=h1; shh[w][e2]=h2;
        __syncwarp();
        float t1 = db0[e1], t2 = db0[e2];
        #pragma unroll
        for (int d=0; d<EE; d++){ float hv=shh[w][d]; t1 += hv*sWd[d*EE+e1]; t2 += hv*sWd[d*EE+e2]; }
        t1 = tanhf(t1); t2 = tanhf(t2);
        float p = warpSum(t1*dW1[e1] + t2*dW1[e2]);
        if (lane==0){
            float nwv = p + db1[0];
            g_nw[gn] = nwv;
            unsigned u = __float_as_uint(nwv);
            u = (u & 0x80000000u) ? ~u : (u | 0x80000000u);
            atomicMax(&g_gmaxu[gn>>11], u);
        }
        float u1 = ub0[e1], u2 = ub0[e2];
        #pragma unroll
        for (int d=0; d<EE; d++){ float hv=shh[w][d]; u1 += hv*sWu[d*EE+e1]; u2 += hv*sWu[d*EE+e2]; }
        u1 = tanhf(u1); u2 = tanhf(u2);
        float q = warpSum(u1*uW1[e1] + u2*uW1[e2]);
        if (lane==0) g_dv[gn] = q + ub1[0];
        __syncwarp();
    }
}

// ---------------- softmax denominators + exp(nw) ----------------
__global__ __launch_bounds__(256) void K_prop(){
    int w = threadIdx.x>>5, lane = threadIdx.x&31;
    int gn = blockIdx.x*8 + w;
    int b = gn >> 11;
    unsigned u = g_gmaxu[b];
    float gm = __uint_as_float((u & 0x80000000u) ? (u ^ 0x80000000u) : ~u);
    int deg = g_deg_adj[gn];
    const unsigned short* list = g_nbr_adj + (size_t)gn*MAXDEG_ADJ;
    float s = 0.f;
    for (int t=lane; t<deg; t+=32) s += __expf(g_nw[b*NN + list[t]] - gm);
    s = warpSum(s);
    if (lane==0){
        g_Z[gn] = (deg>0) ? s : 1.0f;
        g_enw[gn] = __expf(g_nw[gn] - gm);
    }
}

// ---------------- fused 10-iteration MCF, reverse-CSR gather --------------
__global__ __launch_bounds__(1024) void K_flow(const float* __restrict__ demands){
    int b = blockIdx.x;
    __shared__ float us[NN];
    int n1 = threadIdx.x, n2 = threadIdx.x + 1024;
    int gn1 = b*NN+n1, gn2 = b*NN+n2;
    float invZ1 = 1.0f/g_Z[gn1], invZ2 = 1.0f/g_Z[gn2];
    float d1 = demands[gn1], d2 = demands[gn2];
    float e1 = g_enw[gn1],  e2 = g_enw[gn2];
    int rd1 = min(g_rdeg[gn1], MAXDEG_IN);
    int rd2 = min(g_rdeg[gn2], MAXDEG_IN);
    const unsigned short* l1 = g_rin + (size_t)gn1*MAXDEG_IN;
    const unsigned short* l2 = g_rin + (size_t)gn2*MAXDEG_IN;
    float s1 = 0.f, s2 = 0.f;
    for (int it=0; it<10; it++){
        us[n1] = s1*invZ1; us[n2] = s2*invZ2;
        __syncthreads();
        float a1 = 0.f, a2 = 0.f;
        for (int t=0; t<rd1; t++) a1 += us[l1[t]];
        for (int t=0; t<rd2; t++) a2 += us[l2[t]];
        s1 = fmaxf(fmaf(e1, a1, -d1), 0.f);
        s2 = fmaxf(fmaf(e2, a2, -d2), 0.f);
        __syncthreads();
    }
    g_s10[gn1] = s1;
    g_s10[gn2] = s2;
}

// ---------------- flow cost + dual iterations + final reduction ----------
__global__ __launch_bounds__(256) void K_final(const float* __restrict__ demands,
                                               float* __restrict__ out){
    int b = blockIdx.y;
    int tid = threadIdx.x, w = tid>>5, lane = tid&31;
    float acc = 0.f;
    for (int idx = w; idx < 64; idx += 8){
        int n = blockIdx.x*64 + idx;
        int gn = b*NN+n;
        int deg = g_deg_adj[gn];
        const unsigned short* list = g_nbr_adj + (size_t)gn*MAXDEG_ADJ;
        float si = g_s10[gn];
        float invZi = 1.0f/g_Z[gn];
        float dvi = g_dv[gn];
        float enwi = g_enw[gn];
        if (lane==0) acc += dvi * demands[gn];
        int word_idx = (n>>7)*4 + (n&3);
        int bit_idx  = (n>>2)&31;
        for (int t=lane; t<deg; t+=32){
            int j = list[t];
            int gj = b*NN+j;
            float f = g_enw[gj]*invZi*si;
            unsigned word = g_adjbit[(size_t)gj*(NN/32) + word_idx];
            float ft = 0.f;
            if ((word >> bit_idx) & 1u) ft = enwi * (g_s10[gj]/g_Z[gj]);
            float fp = f - fminf(f, ft);
            acc += fp*fp;
            float dd = dvi - g_dv[gj];
            float y = 0.f, m = 0.f;
            #pragma unroll
            for (int q=0; q<10; q++){
                float gg = 2.0f*y - dd;
                m = 0.9f*m + gg;
                y = fmaxf(y - 0.1f*m, 0.f);
            }
            acc -= (y*y - dd*y);
        }
    }
    acc = warpSum(acc);
    __shared__ float sr[8];
    if (lane==0) sr[w] = acc;
    __syncthreads();
    if (tid==0){
        float t = 0.f; for (int i=0;i<8;i++) t += sr[i];
        atomicAdd(&out[b], t);
    }
}

// ---------------- launch ----------------
extern "C" void kernel_launch(void* const* d_in, const int* in_sizes, int n_in,
                              void* d_out, int out_size){
    const float* feat    = (const float*)d_in[0];
    const float* emb     = (const float*)d_in[1];
    const float* demands = (const float*)d_in[2];
    const float* neigh   = (const float*)d_in[4];
    const float* enc_W0  = (const float*)d_in[5];
    const float* enc_b0  = (const float*)d_in[6];
    const float* enc_W1  = (const float*)d_in[7];
    const float* enc_b1  = (const float*)d_in[8];
    const float* attn_W  = (const float*)d_in[9];
    const float* a_src   = (const float*)d_in[10];
    const float* a_dst   = (const float*)d_in[11];
    const float* nbr_q   = (const float*)d_in[12];
    const float* gru_W   = (const float*)d_in[13];
    const float* gru_U   = (const float*)d_in[14];
    const float* gru_b   = (const float*)d_in[15];
    const float* dec_W0  = (const float*)d_in[16];
    const float* dec_b0  = (const float*)d_in[17];
    const float* dec_W1  = (const float*)d_in[18];
    const float* dec_b1  = (const float*)d_in[19];
    const float* dual_W0 = (const float*)d_in[20];
    const float* dual_b0 = (const float*)d_in[21];
    const float* dual_W1 = (const float*)d_in[22];
    const float* dual_b1 = (const float*)d_in[23];
    float* out = (float*)d_out;

    static int configured = 0;
    if (!configured){
        cudaFuncSetAttribute(K_gru, cudaFuncAttributeMaxDynamicSharedMemorySize, GRU_SMEM);
        configured = 1;
    }

    // NOTE: ncu window captures the 4th launch -> K_agg_a2 (layer 0)
    K_enc<<<BB*NN/4,256>>>(emb, feat, enc_W0, enc_b0, enc_W1, enc_b1, out);
    K_build<<<KK*BB*NN/8,256>>>(neigh);
    for (int l=0;l<2;l++){
        K_z<<<dim3(BB*NN/32,HH),256>>>(attn_W, a_src, a_dst);
        K_agg_a2<<<BB*NN,256>>>();
        K_agg_adj<<<BB*NN/8,256>>>();
        K_gru<<<BB*NN/32,256, GRU_SMEM>>>(nbr_q, gru_W, gru_U, gru_b);
    }
    K_dec_dual<<<BB*NN/16,256>>>(dec_W0,dec_b0,dec_W1,dec_b1,dual_W0,dual_b0,dual_W1,dual_b1);
    K_prop<<<BB*NN/8,256>>>();
    K_flow<<<BB,1024>>>(demands);
    K_final<<<dim3(NN/64,BB),256>>>(demands, out);
}

// round 16
// speedup vs baseline: 1.1205x; 1.0272x over previous
#include <cuda_runtime.h>
#include <cuda_bf16.h>
#include <math.h>

#define BB 2
#define NN 2048
#define EE 64
#define HH 2
#define KK 2
#define FIN 18
#define MAXDEG_ADJ 64
#define MAXDEG_A2 512
#define MAXDEG_IN 64
#define FULLMASK 0xffffffffu

// ---------------- device scratch (static, no allocation) ----------------
__device__ float g_h[BB*NN*EE];
__device__ __align__(256) __nv_bfloat16 g_zb[BB*NN*2*EE];  // bf16 z, packed [h0 e0..63 | h1 e0..63]
__device__ float g_ssrc[HH*BB*NN];
__device__ float g_sdst[HH*BB*NN];
__device__ float g_aggs[BB*NN*KK*EE];
__device__ unsigned short g_nbr_adj[BB*NN*MAXDEG_ADJ];
__device__ unsigned short g_nbr_a2[BB*NN*MAXDEG_A2];
__device__ unsigned short g_rin[BB*NN*MAXDEG_IN];
__device__ int g_deg_adj[BB*NN];
__device__ int g_deg_a2[BB*NN];
__device__ int g_rdeg[BB*NN];
// adjbit layout: word = (col>>7)*4 + (col&3), bit = (col>>2)&31
__device__ unsigned g_adjbit[BB*NN*(NN/32)];
__device__ float g_nw[BB*NN];
__device__ float g_dv[BB*NN];
__device__ float g_enw[BB*NN];
__device__ float g_Z[BB*NN];
__device__ float g_s10[BB*NN];
__device__ unsigned g_gmaxu[BB];

__device__ __forceinline__ float warpSum(float v){
    #pragma unroll
    for (int o=16;o;o>>=1) v += __shfl_xor_sync(FULLMASK, v, o);
    return v;
}
__device__ __forceinline__ float sigmoidf_(float x){ return 1.0f/(1.0f+__expf(-x)); }

// ---------------- encoder (+ prelude zeroing of counters/out) -------------
__global__ __launch_bounds__(256) void K_enc(const float* __restrict__ emb,
                                             const float* __restrict__ feat,
                                             const float* __restrict__ W0,
                                             const float* __restrict__ b0,
                                             const float* __restrict__ W1,
                                             const float* __restrict__ b1,
                                             float* __restrict__ out){
    int zidx = blockIdx.x*256 + threadIdx.x;
    if (zidx < BB*NN) g_rdeg[zidx] = 0;
    if (blockIdx.x == 0 && threadIdx.x < BB){ out[threadIdx.x] = 0.f; g_gmaxu[threadIdx.x] = 0u; }

    __shared__ float sW0[FIN*EE];
    __shared__ float sW1[EE*EE];
    __shared__ float sx[4][FIN];
    __shared__ float st[4][EE];
    int tid = threadIdx.x;
    for (int i = tid; i < FIN*EE; i += 256) sW0[i] = W0[i];
    for (int i = tid; i < EE*EE;  i += 256) sW1[i] = W1[i];
    int g = tid >> 6, e = tid & 63;
    int gn = blockIdx.x*4 + g;
    if (e < 16)       sx[g][e]   = emb[gn*16 + e];
    else if (e < 18)  sx[g][e]   = feat[gn*2 + (e-16)];
    __syncthreads();
    float acc = b0[e];
    #pragma unroll
    for (int d=0; d<FIN; d++) acc += sx[g][d]*sW0[d*EE+e];
    st[g][e] = tanhf(acc);
    __syncthreads();
    float acc2 = b1[e];
    #pragma unroll
    for (int d=0; d<EE; d++) acc2 += st[g][d]*sW1[d*EE+e];
    g_h[gn*EE+e] = tanhf(acc2);
}

// ---------------- CSR + bitset + reverse-CSR build (float4) ---------------
__global__ __launch_bounds__(256) void K_build(const float* __restrict__ neigh){
    int lane = threadIdx.x & 31;
    int row = blockIdx.x*8 + (threadIdx.x >> 5);
    int k  = row / (BB*NN);
    int bn = row % (BB*NN);
    int b_ = bn / NN, i_ = bn % NN;
    const float4* src4 = (const float4*)(neigh + (size_t)row * NN);
    unsigned short* dst = (k==0) ? (g_nbr_adj + (size_t)bn*MAXDEG_ADJ)
                                 : (g_nbr_a2  + (size_t)bn*MAXDEG_A2);
    int cap = (k==0) ? MAXDEG_ADJ : MAXDEG_A2;
    int deg = 0;
    unsigned below = (1u<<lane)-1u;
    #pragma unroll 2
    for (int c=0; c<NN/128; c++){
        float4 v = src4[c*32 + lane];
        bool p0 = v.x>0.0f, p1 = v.y>0.0f, p2 = v.z>0.0f, p3 = v.w>0.0f;
        unsigned ba0 = __ballot_sync(FULLMASK, p0);
        unsigned ba1 = __ballot_sync(FULLMASK, p1);
        unsigned ba2 = __ballot_sync(FULLMASK, p2);
        unsigned ba3 = __ballot_sync(FULLMASK, p3);
        if (k==0 && lane<4){
            unsigned sel = (lane==0)?ba0:(lane==1)?ba1:(lane==2)?ba2:ba3;
            g_adjbit[(size_t)bn*(NN/32) + c*4 + lane] = sel;
        }
        int base0 = deg;
        int base1 = base0 + __popc(ba0);
        int base2 = base1 + __popc(ba1);
        int base3 = base2 + __popc(ba2);
        int j0 = c*128 + lane*4;
        if (p0){ int p = base0 + __popc(ba0&below); if (p<cap) dst[p] = (unsigned short)j0;
                 if (k==0){ int rp = atomicAdd(&g_rdeg[b_*NN+j0],1); if (rp<MAXDEG_IN) g_rin[(size_t)(b_*NN+j0)*MAXDEG_IN+rp]=(unsigned short)i_; } }
        if (p1){ int p = base1 + __popc(ba1&below); if (p<cap) dst[p] = (unsigned short)(j0+1);
                 if (k==0){ int rp = atomicAdd(&g_rdeg[b_*NN+j0+1],1); if (rp<MAXDEG_IN) g_rin[(size_t)(b_*NN+j0+1)*MAXDEG_IN+rp]=(unsigned short)i_; } }
        if (p2){ int p = base2 + __popc(ba2&below); if (p<cap) dst[p] = (unsigned short)(j0+2);
                 if (k==0){ int rp = atomicAdd(&g_rdeg[b_*NN+j0+2],1); if (rp<MAXDEG_IN) g_rin[(size_t)(b_*NN+j0+2)*MAXDEG_IN+rp]=(unsigned short)i_; } }
        if (p3){ int p = base3 + __popc(ba3&below); if (p<cap) dst[p] = (unsigned short)(j0+3);
                 if (k==0){ int rp = atomicAdd(&g_rdeg[b_*NN+j0+3],1); if (rp<MAXDEG_IN) g_rin[(size_t)(b_*NN+j0+3)*MAXDEG_IN+rp]=(unsigned short)i_; } }
        deg = base3 + __popc(ba3);
    }
    if (lane==0){
        if (deg > cap) deg = cap;
        if (k==0) g_deg_adj[bn] = deg; else g_deg_a2[bn] = deg;
    }
}

// ---------------- z projection (bf16 out) + attention logits --------------
__global__ __launch_bounds__(256) void K_z(const float* __restrict__ attn_W,
                                           const float* __restrict__ a_src,
                                           const float* __restrict__ a_dst){
    int h = blockIdx.y;
    __shared__ __align__(16) float sW[EE*EE];
    __shared__ __align__(16) float sh[32][68];
    int tid = threadIdx.x;
    const float* W = attn_W + h*EE*EE;
    for (int i=tid;i<EE*EE;i+=256) sW[i] = W[i];
    int gn0 = blockIdx.x*32;
    for (int i=tid;i<32*EE;i+=256) sh[i>>6][i&63] = g_h[(size_t)gn0*EE + i];
    __syncthreads();
    int eg = tid & 15;
    int ng = tid >> 4;
    int n0 = ng*2, n1 = ng*2+1;
    float4 acc0 = {0,0,0,0}, acc1 = {0,0,0,0};
    const float4* sW4 = (const float4*)sW;
    #pragma unroll 4
    for (int d=0; d<EE; d++){
        float4 wv = sW4[d*16 + eg];
        float h0 = sh[n0][d];
        float h1 = sh[n1][d];
        acc0.x += h0*wv.x; acc0.y += h0*wv.y; acc0.z += h0*wv.z; acc0.w += h0*wv.w;
        acc1.x += h1*wv.x; acc1.y += h1*wv.y; acc1.z += h1*wv.z; acc1.w += h1*wv.w;
    }
    {
        __nv_bfloat162 b01 = __floats2bfloat162_rn(acc0.x, acc0.y);
        __nv_bfloat162 b23 = __floats2bfloat162_rn(acc0.z, acc0.w);
        uint2 u; u.x = *(unsigned*)&b01; u.y = *(unsigned*)&b23;
        *(uint2*)(g_zb + ((size_t)(gn0+n0))*2*EE + h*EE + eg*4) = u;
        b01 = __floats2bfloat162_rn(acc1.x, acc1.y);
        b23 = __floats2bfloat162_rn(acc1.z, acc1.w);
        u.x = *(unsigned*)&b01; u.y = *(unsigned*)&b23;
        *(uint2*)(g_zb + ((size_t)(gn0+n1))*2*EE + h*EE + eg*4) = u;
    }
    const float4* as4 = (const float4*)(a_src + h*EE);
    const float4* ad4 = (const float4*)(a_dst + h*EE);
    float4 as = as4[eg], ad = ad4[eg];
    float p0 = acc0.x*as.x + acc0.y*as.y + acc0.z*as.z + acc0.w*as.w;
    float q0 = acc0.x*ad.x + acc0.y*ad.y + acc0.z*ad.z + acc0.w*ad.w;
    float p1 = acc1.x*as.x + acc1.y*as.y + acc1.z*as.z + acc1.w*as.w;
    float q1 = acc1.x*ad.x + acc1.y*ad.y + acc1.z*ad.z + acc1.w*ad.w;
    #pragma unroll
    for (int o=8;o;o>>=1){
        p0 += __shfl_down_sync(FULLMASK, p0, o, 16);
        q0 += __shfl_down_sync(FULLMASK, q0, o, 16);
        p1 += __shfl_down_sync(FULLMASK, p1, o, 16);
        q1 += __shfl_down_sync(FULLMASK, q1, o, 16);
    }
    if (eg == 0){
        g_ssrc[h*BB*NN + gn0 + n0] = p0;
        g_sdst[h*BB*NN + gn0 + n0] = q0;
        g_ssrc[h*BB*NN + gn0 + n1] = p1;
        g_sdst[h*BB*NN + gn0 + n1] = q1;
    }
}

// half-warp gather: lane covers 8 bf16 elements (16 B) at elem0
__device__ __forceinline__ void bf16x8_acc(const __nv_bfloat16* base, int off, int elem0,
                                           float wt, float* a){
    uint4 u = *(const uint4*)(base + off + elem0);
    __nv_bfloat162 h0 = *reinterpret_cast<__nv_bfloat162*>(&u.x);
    __nv_bfloat162 h1 = *reinterpret_cast<__nv_bfloat162*>(&u.y);
    __nv_bfloat162 h2 = *reinterpret_cast<__nv_bfloat162*>(&u.z);
    __nv_bfloat162 h3 = *reinterpret_cast<__nv_bfloat162*>(&u.w);
    float2 f0 = __bfloat1622float2(h0);
    float2 f1 = __bfloat1622float2(h1);
    float2 f2 = __bfloat1622float2(h2);
    float2 f3 = __bfloat1622float2(h3);
    a[0] += wt*f0.x; a[1] += wt*f0.y; a[2] += wt*f1.x; a[3] += wt*f1.y;
    a[4] += wt*f2.x; a[5] += wt*f2.y; a[6] += wt*f3.x; a[7] += wt*f3.y;
}

// ---------------- a2 (k=1) aggregation: block/node, half-warp edges -------
__global__ __launch_bounds__(256) void K_agg_a2(){
    int bn = blockIdx.x;
    int b  = bn >> 11;
    int tid = threadIdx.x, w = tid>>5, lane = tid&31;

    __shared__ float sacc[8][128];
    __shared__ float sw0s[8], sw1s[8];
    __shared__ int sj[8][32];          // pre-scaled element offsets (j*128)
    __shared__ float swt[8][2][32];

    int deg = g_deg_a2[bn];
    const unsigned short* list = g_nbr_a2 + (size_t)bn*MAXDEG_A2;
    const __nv_bfloat16* zb = g_zb + (size_t)b*NN*2*EE;

    int hw = lane >> 4;       // which edge of the pair
    int li = lane & 15;       // element group: elems li*8 .. li*8+7
    int elem0 = li*8;
    int hsel = li >> 3;       // 0: head0 elems, 1: head1 elems
    float a[8] = {0,0,0,0,0,0,0,0};
    float s0=0.f, s1=0.f;
    if (deg == 0){
        for (int j = w*(NN/8) + hw; j < (w+1)*(NN/8); j += 2)
            bf16x8_acc(zb, j*128, elem0, 1.0f, a);
        if (lane == 0){ s0 = (float)(NN/8); s1 = (float)(NN/8); }
    } else {
        float ssrc0 = g_ssrc[bn];
        float ssrc1 = g_ssrc[BB*NN + bn];
        const float* sd0 = g_sdst + b*NN;
        const float* sd1 = g_sdst + BB*NN + b*NN;
        for (int base = w*32; base < deg; base += 256){
            int cnt = deg - base; if (cnt > 32) cnt = 32;
            int jl = 0; float w0l = 0.f, w1l = 0.f;
            if (lane < cnt){
                jl = list[base + lane];
                w0l = __expf(tanhf(ssrc0 + sd0[jl]));
                w1l = __expf(tanhf(ssrc1 + sd1[jl]));
            }
            s0 += w0l; s1 += w1l;
            sj[w][lane] = jl*128;
            swt[w][0][lane] = w0l;
            swt[w][1][lane] = w1l;
            __syncwarp();
            if (cnt == 32){
                #pragma unroll 8
                for (int i=0;i<32;i+=2){
                    int e = i + hw;
                    bf16x8_acc(zb, sj[w][e], elem0, swt[w][hsel][e], a);
                }
            } else {
                int cntp = (cnt+1) & ~1;   // padded lanes have weight 0, offset 0 (valid)
                for (int i=0;i<cntp;i+=2){
                    int e = i + hw;
                    bf16x8_acc(zb, sj[w][e], elem0, swt[w][hsel][e], a);
                }
            }
            __syncwarp();
        }
    }
    s0 = warpSum(s0); s1 = warpSum(s1);
    if (lane==0){ sw0s[w]=s0; sw1s[w]=s1; }
    #pragma unroll
    for (int k=0;k<8;k++) a[k] += __shfl_down_sync(FULLMASK, a[k], 16);
    if (lane < 16){
        #pragma unroll
        for (int k=0;k<8;k++) sacc[w][elem0+k] = a[k];
    }
    __syncthreads();
    if (tid < EE){
        float r0=0.f, r1=0.f, S0=0.f, S1=0.f;
        #pragma unroll
        for (int ww=0; ww<8; ww++){
            r0 += sacc[ww][tid];
            r1 += sacc[ww][64+tid];
            S0 += sw0s[ww]; S1 += sw1s[ww];
        }
        float v = 0.5f*(r0/S0 + r1/S1);
        g_aggs[((size_t)bn*KK + 1)*EE + tid] = tanhf(v);
    }
}

// ---------------- adj (k=0) aggregation: warp/node, half-warp edges -------
__global__ __launch_bounds__(256) void K_agg_adj(){
    int w = threadIdx.x>>5, lane = threadIdx.x&31;
    int bn = blockIdx.x*8 + w;
    int b = bn >> 11;
    __shared__ int sj[8][32];
    __shared__ float swt[8][2][32];
    int deg = g_deg_adj[bn];
    const __nv_bfloat16* zb = g_zb + (size_t)b*NN*2*EE;
    int hw = lane >> 4;
    int li = lane & 15;
    int elem0 = li*8;
    int hsel = li >> 3;
    float a[8] = {0,0,0,0,0,0,0,0};
    float ws0=0.f, ws1=0.f;
    if (deg==0){
        for (int j=hw;j<NN;j+=2) bf16x8_acc(zb, j*128, elem0, 1.0f, a);
        ws0 = (float)NN; ws1 = (float)NN;
    } else {
        const unsigned short* list = g_nbr_adj + (size_t)bn*MAXDEG_ADJ;
        float ssrc0 = g_ssrc[bn], ssrc1 = g_ssrc[BB*NN+bn];
        const float* sd0 = g_sdst + b*NN;
        const float* sd1 = g_sdst + BB*NN + b*NN;
        for (int base=0; base<deg; base+=32){
            int cnt = deg - base; if (cnt>32) cnt=32;
            int jl = 0; float w0 = 0.f, w1 = 0.f;
            if (lane < cnt){
                jl = list[base+lane];
                w0 = __expf(tanhf(ssrc0 + sd0[jl]));
                w1 = __expf(tanhf(ssrc1 + sd1[jl]));
            }
            ws0 += w0; ws1 += w1;
            sj[w][lane] = jl*128;
            swt[w][0][lane]=w0; swt[w][1][lane]=w1;
            __syncwarp();
            int cntp = (cnt+1) & ~1;
            #pragma unroll 4
            for (int i=0;i<cntp;i+=2){
                int e = i + hw;
                bf16x8_acc(zb, sj[w][e], elem0, swt[w][hsel][e], a);
            }
            __syncwarp();
        }
        ws0 = warpSum(ws0); ws1 = warpSum(ws1);
    }
    #pragma unroll
    for (int k=0;k<8;k++) a[k] += __shfl_down_sync(FULLMASK, a[k], 16);
    // lanes 0-7 hold head0 elems (e=li*8+k), lanes 8-15 head1
    float bvals[8];
    #pragma unroll
    for (int k=0;k<8;k++) bvals[k] = __shfl_sync(FULLMASK, a[k], lane+8);
    if (lane < 8){
        float inv0 = 1.0f/ws0, inv1 = 1.0f/ws1;
        float4 o1, o2;
        o1.x = tanhf(0.5f*(a[0]*inv0 + bvals[0]*inv1));
        o1.y = tanhf(0.5f*(a[1]*inv0 + bvals[1]*inv1));
        o1.z = tanhf(0.5f*(a[2]*inv0 + bvals[2]*inv1));
        o1.w = tanhf(0.5f*(a[3]*inv0 + bvals[3]*inv1));
        o2.x = tanhf(0.5f*(a[4]*inv0 + bvals[4]*inv1));
        o2.y = tanhf(0.5f*(a[5]*inv0 + bvals[5]*inv1));
        o2.z = tanhf(0.5f*(a[6]*inv0 + bvals[6]*inv1));
        o2.w = tanhf(0.5f*(a[7]*inv0 + bvals[7]*inv1));
        float* dstp = g_aggs + ((size_t)bn*KK+0)*EE + lane*8;
        *(float4*)dstp = o1;
        *(float4*)(dstp+4) = o2;
    }
}

// ---------------- GRU as register-tiled GEMM (32 nodes/block) -------------
#define XS 132
#define ZS 68
__global__ __launch_bounds__(256) void K_gru(const float* __restrict__ nbr_q,
                                             const float* __restrict__ gru_W,
                                             const float* __restrict__ gru_U,
                                             const float* __restrict__ gru_b){
    extern __shared__ __align__(16) float dyn[];
    float* WA = dyn;                 // 128*128
    float* WB = dyn + 16384;         // 128*64
    float* X  = dyn + 24576;         // 32*XS
    float* SZ = X + 32*XS;           // 32*ZS (z gate)
    float* HO = SZ + 32*ZS;          // 32*ZS (h_old)
    int tid = threadIdx.x, w = tid>>5, lane = tid&31;

    for (int i=tid; i<128*128; i+=256){
        int d = i>>7, e = i&127;
        WA[i] = (d<64) ? gru_W[d*192+e] : gru_U[(d-64)*192+e];
    }
    for (int i=tid; i<128*64; i+=256){
        int d = i>>6, e = i&63;
        WB[i] = (d<64) ? gru_W[d*192+128+e] : gru_U[(d-64)*192+128+e];
    }

    int gn0 = blockIdx.x*32;
    for (int r=0; r<4; r++){
        int ln = w*4 + r;
        int gn = gn0 + ln;
        const float* ag = g_aggs + (size_t)gn*KK*EE;
        float a0_1 = ag[lane],     a0_2 = ag[32+lane];
        float a1_1 = ag[64+lane],  a1_2 = ag[96+lane];
        float q1 = nbr_q[lane], q2 = nbr_q[32+lane];
        float d0 = warpSum(a0_1*q1 + a0_2*q2);
        float d1 = warpSum(a1_1*q1 + a1_2*q2);
        float t0 = tanhf(d0), t1 = tanhf(d1);
        float mx = fmaxf(t0,t1);
        float ex0 = __expf(t0-mx), ex1 = __expf(t1-mx);
        float inv = 1.0f/(ex0+ex1);
        float c0 = ex0*inv, c1 = ex1*inv;
        float h1 = g_h[(size_t)gn*EE+lane], h2 = g_h[(size_t)gn*EE+32+lane];
        X[ln*XS+lane]      = c0*a0_1 + c1*a1_1;
        X[ln*XS+32+lane]   = c0*a0_2 + c1*a1_2;
        X[ln*XS+64+lane]   = h1;
        X[ln*XS+96+lane]   = h2;
        HO[ln*ZS+lane]     = h1;
        HO[ln*ZS+32+lane]  = h2;
    }
    __syncthreads();

    int ng = tid & 7;
    int eg = tid >> 3;

    float4 acA0={0,0,0,0}, acA1={0,0,0,0}, acA2={0,0,0,0}, acA3={0,0,0,0};
    {
        const float4* WA4 = (const float4*)WA;
        const float* x0p = X + ng*XS;
        const float* x1p = X + (ng+8)*XS;
        const float* x2p = X + (ng+16)*XS;
        const float* x3p = X + (ng+24)*XS;
        #pragma unroll 4
        for (int d=0; d<128; d++){
            float4 wv = WA4[d*32 + eg];
            float x0 = x0p[d], x1 = x1p[d], x2 = x2p[d], x3 = x3p[d];
            acA0.x += x0*wv.x; acA0.y += x0*wv.y; acA0.z += x0*wv.z; acA0.w += x0*wv.w;
            acA1.x += x1*wv.x; acA1.y += x1*wv.y; acA1.z += x1*wv.z; acA1.w += x1*wv.w;
            acA2.x += x2*wv.x; acA2.y += x2*wv.y; acA2.z += x2*wv.z; acA2.w += x2*wv.w;
            acA3.x += x3*wv.x; acA3.y += x3*wv.y; acA3.z += x3*wv.z; acA3.w += x3*wv.w;
        }
    }
    __syncthreads();
    {
        int e0 = eg*4;
        float b0v = gru_b[e0], b1v = gru_b[e0+1], b2v = gru_b[e0+2], b3v = gru_b[e0+3];
        float4 accs[4] = {acA0, acA1, acA2, acA3};
        #pragma unroll
        for (int k=0;k<4;k++){
            int n = ng + k*8;
            float v0 = sigmoidf_(accs[k].x + b0v);
            float v1 = sigmoidf_(accs[k].y + b1v);
            float v2 = sigmoidf_(accs[k].z + b2v);
            float v3 = sigmoidf_(accs[k].w + b3v);
            if (e0 < 64){
                SZ[n*ZS+e0]=v0; SZ[n*ZS+e0+1]=v1; SZ[n*ZS+e0+2]=v2; SZ[n*ZS+e0+3]=v3;
            } else {
                int c = e0;
                X[n*XS+c]   = v0 * X[n*XS+c];
                X[n*XS+c+1] = v1 * X[n*XS+c+1];
                X[n*XS+c+2] = v2 * X[n*XS+c+2];
                X[n*XS+c+3] = v3 * X[n*XS+c+3];
            }
        }
    }
    __syncthreads();

    float acB0x=0,acB0y=0, acB1x=0,acB1y=0, acB2x=0,acB2y=0, acB3x=0,acB3y=0;
    {
        const float2* WB2 = (const float2*)WB;
        const float* x0p = X + ng*XS;
        const float* x1p = X + (ng+8)*XS;
        const float* x2p = X + (ng+16)*XS;
        const float* x3p = X + (ng+24)*XS;
        #pragma unroll 4
        for (int d=0; d<128; d++){
            float2 wv = WB2[d*32 + eg];
            float x0 = x0p[d], x1 = x1p[d], x2 = x2p[d], x3 = x3p[d];
            acB0x += x0*wv.x; acB0y += x0*wv.y;
            acB1x += x1*wv.x; acB1y += x1*wv.y;
            acB2x += x2*wv.x; acB2y += x2*wv.y;
            acB3x += x3*wv.x; acB3y += x3*wv.y;
        }
    }
    {
        int e0 = eg*2;
        float bb0 = gru_b[128+e0], bb1 = gru_b[128+e0+1];
        float bx[4] = {acB0x, acB1x, acB2x, acB3x};
        float by[4] = {acB0y, acB1y, acB2y, acB3y};
        #pragma unroll
        for (int k=0;k<4;k++){
            int n = ng + k*8;
            int gn = gn0 + n;
            float ht0 = tanhf(bx[k] + bb0);
            float ht1 = tanhf(by[k] + bb1);
            float z0 = SZ[n*ZS+e0], z1 = SZ[n*ZS+e0+1];
            float h0 = HO[n*ZS+e0], h1 = HO[n*ZS+e0+1];
            g_h[(size_t)gn*EE+e0]   = (1.0f-z0)*h0 + z0*ht0;
            g_h[(size_t)gn*EE+e0+1] = (1.0f-z1)*h1 + z1*ht1;
        }
    }
}
#define GRU_SMEM ((16384 + 128*64 + 32*XS + 2*32*ZS)*4)

// ---------------- decoder + dual heads + gmax ----------------
__global__ __launch_bounds__(256) void K_dec_dual(const float* __restrict__ dW0, const float* __restrict__ db0,
                                                  const float* __restrict__ dW1, const float* __restrict__ db1,
                                                  const float* __restrict__ uW0, const float* __restrict__ ub0,
                                                  const float* __restrict__ uW1, const float* __restrict__ ub1){
    __shared__ float sWd[EE*EE];
    __shared__ float sWu[EE*EE];
    __shared__ float shh[8][EE];
    int tid = threadIdx.x;
    for (int i=tid;i<EE*EE;i+=256){ sWd[i]=dW0[i]; sWu[i]=uW0[i]; }
    __syncthreads();
    int w = tid>>5, lane = tid&31;
    int e1 = lane, e2 = lane+32;
    #pragma unroll
    for (int rep=0; rep<2; rep++){
        int gn = blockIdx.x*16 + w + rep*8;
        float h1 = g_h[(size_t)gn*EE+e1], h2 = g_h[(size_t)gn*EE+e2];
        shh[w][e1]=h1; shh[w][e2]=h2;
        __syncwarp();
        float t1 = db0[e1], t2 = db0[e2];
        #pragma unroll
        for (int d=0; d<EE; d++){ float hv=shh[w][d]; t1 += hv*sWd[d*EE+e1]; t2 += hv*sWd[d*EE+e2]; }
        t1 = tanhf(t1); t2 = tanhf(t2);
        float p = warpSum(t1*dW1[e1] + t2*dW1[e2]);
        if (lane==0){
            float nwv = p + db1[0];
            g_nw[gn] = nwv;
            unsigned u = __float_as_uint(nwv);
            u = (u & 0x80000000u) ? ~u : (u | 0x80000000u);
            atomicMax(&g_gmaxu[gn>>11], u);
        }
        float u1 = ub0[e1], u2 = ub0[e2];
        #pragma unroll
        for (int d=0; d<EE; d++){ float hv=shh[w][d]; u1 += hv*sWu[d*EE+e1]; u2 += hv*sWu[d*EE+e2]; }
        u1 = tanhf(u1); u2 = tanhf(u2);
        float q = warpSum(u1*uW1[e1] + u2*uW1[e2]);
        if (lane==0) g_dv[gn] = q + ub1[0];
        __syncwarp();
    }
}

// ---------------- softmax denominators + exp(nw) ----------------
__global__ __launch_bounds__(256) void K_prop(){
    int w = threadIdx.x>>5, lane = threadIdx.x&31;
    int gn = blockIdx.x*8 + w;
    int b = gn >> 11;
    unsigned u = g_gmaxu[b];
    float gm = __uint_as_float((u & 0x80000000u) ? (u ^ 0x80000000u) : ~u);
    int deg = g_deg_adj[gn];
    const unsigned short* list = g_nbr_adj + (size_t)gn*MAXDEG_ADJ;
    float s = 0.f;
    for (int t=lane; t<deg; t+=32) s += __expf(g_nw[b*NN + list[t]] - gm);
    s = warpSum(s);
    if (lane==0){
        g_Z[gn] = (deg>0) ? s : 1.0f;
        g_enw[gn] = __expf(g_nw[gn] - gm);
    }
}

// ---------------- fused 10-iteration MCF, reverse-CSR gather --------------
__global__ __launch_bounds__(1024) void K_flow(const float* __restrict__ demands){
    int b = blockIdx.x;
    __shared__ float us[NN];
    int n1 = threadIdx.x, n2 = threadIdx.x + 1024;
    int gn1 = b*NN+n1, gn2 = b*NN+n2;
    float invZ1 = 1.0f/g_Z[gn1], invZ2 = 1.0f/g_Z[gn2];
    float d1 = demands[gn1], d2 = demands[gn2];
    float e1 = g_enw[gn1],  e2 = g_enw[gn2];
    int rd1 = min(g_rdeg[gn1], MAXDEG_IN);
    int rd2 = min(g_rdeg[gn2], MAXDEG_IN);
    const unsigned short* l1 = g_rin + (size_t)gn1*MAXDEG_IN;
    const unsigned short* l2 = g_rin + (size_t)gn2*MAXDEG_IN;
    float s1 = 0.f, s2 = 0.f;
    for (int it=0; it<10; it++){
        us[n1] = s1*invZ1; us[n2] = s2*invZ2;
        __syncthreads();
        float a1 = 0.f, a2 = 0.f;
        for (int t=0; t<rd1; t++) a1 += us[l1[t]];
        for (int t=0; t<rd2; t++) a2 += us[l2[t]];
        s1 = fmaxf(fmaf(e1, a1, -d1), 0.f);
        s2 = fmaxf(fmaf(e2, a2, -d2), 0.f);
        __syncthreads();
    }
    g_s10[gn1] = s1;
    g_s10[gn2] = s2;
}

// ---------------- flow cost + dual iterations + final reduction ----------
// 256 blocks: 16 nodes per block (was 64) for full-chip latency hiding
__global__ __launch_bounds__(256) void K_final(const float* __restrict__ demands,
                                               float* __restrict__ out){
    int b = blockIdx.y;
    int tid = threadIdx.x, w = tid>>5, lane = tid&31;
    float acc = 0.f;
    for (int idx = w; idx < 16; idx += 8){
        int n = blockIdx.x*16 + idx;
        int gn = b*NN+n;
        int deg = g_deg_adj[gn];
        const unsigned short* list = g_nbr_adj + (size_t)gn*MAXDEG_ADJ;
        float si = g_s10[gn];
        float invZi = 1.0f/g_Z[gn];
        float dvi = g_dv[gn];
        float enwi = g_enw[gn];
        if (lane==0) acc += dvi * demands[gn];
        int word_idx = (n>>7)*4 + (n&3);
        int bit_idx  = (n>>2)&31;
        for (int t=lane; t<deg; t+=32){
            int j = list[t];
            int gj = b*NN+j;
            float f = g_enw[gj]*invZi*si;
            unsigned word = g_adjbit[(size_t)gj*(NN/32) + word_idx];
            float ft = 0.f;
            if ((word >> bit_idx) & 1u) ft = enwi * (g_s10[gj]/g_Z[gj]);
            float fp = f - fminf(f, ft);
            acc += fp*fp;
            float dd = dvi - g_dv[gj];
            float y = 0.f, m = 0.f;
            #pragma unroll
            for (int q=0; q<10; q++){
                float gg = 2.0f*y - dd;
                m = 0.9f*m + gg;
                y = fmaxf(y - 0.1f*m, 0.f);
            }
            acc -= (y*y - dd*y);
        }
    }
    acc = warpSum(acc);
    __shared__ float sr[8];
    if (lane==0) sr[w] = acc;
    __syncthreads();
    if (tid==0){
        float t = 0.f; for (int i=0;i<8;i++) t += sr[i];
        atomicAdd(&out[b], t);
    }
}

// ---------------- launch ----------------
extern "C" void kernel_launch(void* const* d_in, const int* in_sizes, int n_in,
                              void* d_out, int out_size){
    const float* feat    = (const float*)d_in[0];
    const float* emb     = (const float*)d_in[1];
    const float* demands = (const float*)d_in[2];
    const float* neigh   = (const float*)d_in[4];
    const float* enc_W0  = (const float*)d_in[5];
    const float* enc_b0  = (const float*)d_in[6];
    const float* enc_W1  = (const float*)d_in[7];
    const float* enc_b1  = (const float*)d_in[8];
    const float* attn_W  = (const float*)d_in[9];
    const float* a_src   = (const float*)d_in[10];
    const float* a_dst   = (const float*)d_in[11];
    const float* nbr_q   = (const float*)d_in[12];
    const float* gru_W   = (const float*)d_in[13];
    const float* gru_U   = (const float*)d_in[14];
    const float* gru_b   = (const float*)d_in[15];
    const float* dec_W0  = (const float*)d_in[16];
    const float* dec_b0  = (const float*)d_in[17];
    const float* dec_W1  = (const float*)d_in[18];
    const float* dec_b1  = (const float*)d_in[19];
    const float* dual_W0 = (const float*)d_in[20];
    const float* dual_b0 = (const float*)d_in[21];
    const float* dual_W1 = (const float*)d_in[22];
    const float* dual_b1 = (const float*)d_in[23];
    float* out = (float*)d_out;

    static int configured = 0;
    if (!configured){
        cudaFuncSetAttribute(K_gru, cudaFuncAttributeMaxDynamicSharedMemorySize, GRU_SMEM);
        configured = 1;
    }

    // NOTE: ncu window captures the 4th launch -> K_agg_a2 (layer 0)
    K_enc<<<BB*NN/4,256>>>(emb, feat, enc_W0, enc_b0, enc_W1, enc_b1, out);
    K_build<<<KK*BB*NN/8,256>>>(neigh);
    for (int l=0;l<2;l++){
        K_z<<<dim3(BB*NN/32,HH),256>>>(attn_W, a_src, a_dst);
        K_agg_a2<<<BB*NN,256>>>();
        K_agg_adj<<<BB*NN/8,256>>>();
        K_gru<<<BB*NN/32,256, GRU_SMEM>>>(nbr_q, gru_W, gru_U, gru_b);
    }
    K_dec_dual<<<BB*NN/16,256>>>(dec_W0,dec_b0,dec_W1,dec_b1,dual_W0,dual_b0,dual_W1,dual_b1);
    K_prop<<<BB*NN/8,256>>>();
    K_flow<<<BB,1024>>>(demands);
    K_final<<<dim3(NN/16,BB),256>>>(demands, out);
}